// round 1
// baseline (speedup 1.0000x reference)
#include <cuda_runtime.h>

#define NN 20000
#define NE 160000

// ---------------- scratch (device globals: allocation-free) ----------------
__device__ float g_xl1[NN * 128];
__device__ float g_xr1[NN * 128];
__device__ float g_h1 [NN * 128];
__device__ float g_xl2[NN * 512];
__device__ float g_xr2[NN * 512];
__device__ float g_h2 [NN * 512];
__device__ int   g_deg[NN];
__device__ int   g_rowptr[NN + 1];
__device__ int   g_cursor[NN];
__device__ int   g_col[NE];

// ---------------- CSR build (counting sort by dst) ----------------
__global__ void k_zero_deg() {
    int i = blockIdx.x * blockDim.x + threadIdx.x;
    if (i < NN) g_deg[i] = 0;
}

__global__ void k_hist(const int* __restrict__ dst) {
    int e = blockIdx.x * blockDim.x + threadIdx.x;
    if (e < NE) atomicAdd(&g_deg[dst[e]], 1);
}

__global__ void k_scan() {
    __shared__ int s[1024];
    const int CH = (NN + 1023) / 1024;  // 20
    int t = threadIdx.x;
    int start = t * CH;
    int end = start + CH < NN ? start + CH : NN;
    int sum = 0;
    for (int i = start; i < end; i++) sum += g_deg[i];
    s[t] = sum;
    __syncthreads();
    for (int off = 1; off < 1024; off <<= 1) {
        int v = (t >= off) ? s[t - off] : 0;
        __syncthreads();
        s[t] += v;
        __syncthreads();
    }
    int run = (t == 0) ? 0 : s[t - 1];
    for (int i = start; i < end; i++) {
        g_rowptr[i] = run;
        g_cursor[i] = run;
        run += g_deg[i];
    }
    if (t == 1023) g_rowptr[NN] = s[1023];
}

__global__ void k_scatter(const int* __restrict__ src, const int* __restrict__ dst) {
    int e = blockIdx.x * blockDim.x + threadIdx.x;
    if (e < NE) {
        int d = dst[e];
        int pos = atomicAdd(&g_cursor[d], 1);
        g_col[pos] = src[e];
    }
}

// ---------------- tiled fp32 GEMM: C = [relu](A[M,K] @ B[K,N] + bias) ----------------
template <int BM, int BN, int BK, int TM, int TN, bool RELU>
__global__ void __launch_bounds__((BM / TM) * (BN / TN))
sgemm(const float* __restrict__ A, const float* __restrict__ B,
      const float* __restrict__ bias, float* __restrict__ C,
      int M, int N, int K) {
    constexpr int THREADS = (BM / TM) * (BN / TN);
    __shared__ float As[BM][BK + 1];
    __shared__ float Bs[BK][BN];

    const int tid = threadIdx.x;
    const int tcols = BN / TN;
    const int trow = tid / tcols;
    const int tcol = tid % tcols;
    const int m0 = blockIdx.y * BM;
    const int n0 = blockIdx.x * BN;

    float acc[TM][TN];
#pragma unroll
    for (int i = 0; i < TM; i++)
#pragma unroll
        for (int j = 0; j < TN; j++) acc[i][j] = 0.f;

    for (int k0 = 0; k0 < K; k0 += BK) {
#pragma unroll
        for (int i = tid; i < BM * BK; i += THREADS) {
            int r = i / BK, c = i % BK;
            int gm = m0 + r;
            As[r][c] = (gm < M) ? A[gm * K + k0 + c] : 0.f;
        }
#pragma unroll
        for (int i = tid; i < BK * BN; i += THREADS) {
            int r = i / BN, c = i % BN;
            int gn = n0 + c;
            Bs[r][c] = (gn < N) ? B[(k0 + r) * N + gn] : 0.f;
        }
        __syncthreads();
#pragma unroll
        for (int k = 0; k < BK; k++) {
            float a[TM], b[TN];
#pragma unroll
            for (int i = 0; i < TM; i++) a[i] = As[trow * TM + i][k];
#pragma unroll
            for (int j = 0; j < TN; j += 4) {
                float4 v = *reinterpret_cast<const float4*>(&Bs[k][tcol * TN + j]);
                b[j] = v.x; b[j + 1] = v.y; b[j + 2] = v.z; b[j + 3] = v.w;
            }
#pragma unroll
            for (int i = 0; i < TM; i++)
#pragma unroll
                for (int j = 0; j < TN; j++)
                    acc[i][j] = fmaf(a[i], b[j], acc[i][j]);
        }
        __syncthreads();
    }

#pragma unroll
    for (int i = 0; i < TM; i++) {
        int gm = m0 + trow * TM + i;
        if (gm < M) {
#pragma unroll
            for (int j = 0; j < TN; j++) {
                int gn = n0 + tcol * TN + j;
                if (gn < N) {
                    float v = acc[i][j] + bias[gn];
                    if (RELU) v = fmaxf(v, 0.f);
                    C[gm * N + gn] = v;
                }
            }
        }
    }
}

// ---------------- fused GATv2 edge-softmax + aggregation ----------------
// One warp per destination node. D = H*C features; lane l owns contiguous
// channels [l*CPL, (l+1)*CPL) which all lie in head l/8. Online softmax per
// head via shfl reduction over the 8-lane head group. xl[src] is read exactly
// once per edge. Output = relu(agg/sum + bias).
template <int D>
__global__ void k_agg(const float* __restrict__ xl, const float* __restrict__ xr,
                      const float* __restrict__ att, const float* __restrict__ bias,
                      float* __restrict__ out) {
    constexpr int CPL = D / 32;   // channels per lane (4 or 16)
    constexpr int V = CPL / 4;    // float4s per lane

    int warp = (blockIdx.x * blockDim.x + threadIdx.x) >> 5;
    int lane = threadIdx.x & 31;
    if (warp >= NN) return;
    const int node = warp;
    const int base = lane * CPL;

    float attv[CPL], xrv[CPL];
#pragma unroll
    for (int j = 0; j < V; j++) {
        float4 a4 = *reinterpret_cast<const float4*>(att + base + 4 * j);
        float4 r4 = *reinterpret_cast<const float4*>(xr + node * D + base + 4 * j);
        attv[4 * j + 0] = a4.x; attv[4 * j + 1] = a4.y;
        attv[4 * j + 2] = a4.z; attv[4 * j + 3] = a4.w;
        xrv[4 * j + 0] = r4.x; xrv[4 * j + 1] = r4.y;
        xrv[4 * j + 2] = r4.z; xrv[4 * j + 3] = r4.w;
    }

    float m = -3.402823466e38f;   // -FLT_MAX
    float ssum = 0.f;
    float acc[CPL];
#pragma unroll
    for (int c = 0; c < CPL; c++) acc[c] = 0.f;

    const int rs = g_rowptr[node];
    const int re = g_rowptr[node + 1];
    for (int p = rs; p < re; p++) {
        int s = g_col[p];
        float xlv[CPL];
#pragma unroll
        for (int j = 0; j < V; j++) {
            float4 v = *reinterpret_cast<const float4*>(xl + s * D + base + 4 * j);
            xlv[4 * j + 0] = v.x; xlv[4 * j + 1] = v.y;
            xlv[4 * j + 2] = v.z; xlv[4 * j + 3] = v.w;
        }
        float partial = 0.f;
#pragma unroll
        for (int c = 0; c < CPL; c++) {
            float e = xlv[c] + xrv[c];
            e = (e >= 0.f) ? e : 0.2f * e;           // LeakyReLU(0.2)
            partial = fmaf(attv[c], e, partial);
        }
        // reduce score across the 8-lane head group
        partial += __shfl_xor_sync(0xffffffffu, partial, 1);
        partial += __shfl_xor_sync(0xffffffffu, partial, 2);
        partial += __shfl_xor_sync(0xffffffffu, partial, 4);

        float mnew = fmaxf(m, partial);
        float fac = __expf(m - mnew);
        float w = __expf(partial - mnew);
        ssum = ssum * fac + w;
#pragma unroll
        for (int c = 0; c < CPL; c++) acc[c] = fmaf(acc[c], fac, w * xlv[c]);
        m = mnew;
    }

    float inv = (ssum > 0.f) ? (1.f / ssum) : 0.f;
#pragma unroll
    for (int c = 0; c < CPL; c++) {
        float v = fmaf(acc[c], inv, bias[base + c]);
        out[node * D + base + c] = fmaxf(v, 0.f);    // ReLU (both GAT layers)
    }
}

// ---------------- launch ----------------
extern "C" void kernel_launch(void* const* d_in, const int* in_sizes, int n_in,
                              void* d_out, int out_size) {
    (void)in_sizes; (void)n_in; (void)out_size;
    const float* x     = (const float*)d_in[0];
    const int*   ei    = (const int*)  d_in[1];
    // d_in[2] = edge_attr (unused by reference)
    const float* Wl1   = (const float*)d_in[3];
    const float* bl1   = (const float*)d_in[4];
    const float* Wr1   = (const float*)d_in[5];
    const float* br1   = (const float*)d_in[6];
    const float* att1  = (const float*)d_in[7];
    const float* bias1 = (const float*)d_in[8];
    const float* Wl2   = (const float*)d_in[9];
    const float* bl2   = (const float*)d_in[10];
    const float* Wr2   = (const float*)d_in[11];
    const float* br2   = (const float*)d_in[12];
    const float* att2  = (const float*)d_in[13];
    const float* bias2 = (const float*)d_in[14];
    const float* Wlin  = (const float*)d_in[15];
    const float* blin  = (const float*)d_in[16];
    float* out = (float*)d_out;

    const int* src = ei;
    const int* dst = ei + NE;

    float *xl1, *xr1, *h1, *xl2, *xr2, *h2;
    cudaGetSymbolAddress((void**)&xl1, g_xl1);
    cudaGetSymbolAddress((void**)&xr1, g_xr1);
    cudaGetSymbolAddress((void**)&h1,  g_h1);
    cudaGetSymbolAddress((void**)&xl2, g_xl2);
    cudaGetSymbolAddress((void**)&xr2, g_xr2);
    cudaGetSymbolAddress((void**)&h2,  g_h2);

    // CSR build
    k_zero_deg<<<(NN + 255) / 256, 256>>>();
    k_hist<<<(NE + 255) / 256, 256>>>(dst);
    k_scan<<<1, 1024>>>();
    k_scatter<<<(NE + 255) / 256, 256>>>(src, dst);

    const int MB = (NN + 127) / 128;  // 157

    // Layer 1 linear transforms
    sgemm<128, 128, 16, 8, 8, false><<<dim3(1, MB), 256>>>(x, Wl1, bl1, xl1, NN, 128, 128);
    sgemm<128, 128, 16, 8, 8, false><<<dim3(1, MB), 256>>>(x, Wr1, br1, xr1, NN, 128, 128);
    // Layer 1 fused attention softmax + aggregate + bias + relu
    k_agg<128><<<NN / 8, 256>>>(xl1, xr1, att1, bias1, h1);

    // Layer 2 linear transforms
    sgemm<128, 128, 16, 8, 8, false><<<dim3(4, MB), 256>>>(h1, Wl2, bl2, xl2, NN, 512, 128);
    sgemm<128, 128, 16, 8, 8, false><<<dim3(4, MB), 256>>>(h1, Wr2, br2, xr2, NN, 512, 128);
    // Layer 2 fused attention
    k_agg<512><<<NN / 8, 256>>>(xl2, xr2, att2, bias2, h2);

    // Output linear
    sgemm<128, 128, 16, 8, 8, false><<<dim3(1, MB), 256>>>(h2, Wlin, blin, out, NN, 64, 512);
}

// round 3
// speedup vs baseline: 1.8408x; 1.8408x over previous
#include <cuda_runtime.h>
#include <cuda_bf16.h>
#include <cstdint>

#define NN 20000
#define NE 160000

// ---------------- scratch (device globals: allocation-free) ----------------
__device__ float g_xl1[NN * 128];
__device__ float g_xr1[NN * 128];
__device__ float g_h1 [NN * 128];
__device__ float g_xl2[NN * 512];
__device__ float g_xr2[NN * 512];
__device__ float g_h2 [NN * 512];
__device__ int   g_deg[NN];
__device__ int   g_rowptr[NN + 1];
__device__ int   g_cursor[NN];
__device__ int   g_col[NE];
__device__ float g_wl1t[128 * 128];
__device__ float g_wr1t[128 * 128];
__device__ float g_wl2t[512 * 128];
__device__ float g_wr2t[512 * 128];
__device__ float g_wlint[64 * 512];

// ---------------- CSR build (counting sort by dst) ----------------
__global__ void k_zero_deg() {
    int i = blockIdx.x * blockDim.x + threadIdx.x;
    if (i < NN) g_deg[i] = 0;
}
__global__ void k_hist(const int* __restrict__ dst) {
    int e = blockIdx.x * blockDim.x + threadIdx.x;
    if (e < NE) atomicAdd(&g_deg[dst[e]], 1);
}
__global__ void k_scan() {
    __shared__ int s[1024];
    const int CH = (NN + 1023) / 1024;
    int t = threadIdx.x;
    int start = t * CH;
    int end = start + CH < NN ? start + CH : NN;
    int sum = 0;
    for (int i = start; i < end; i++) sum += g_deg[i];
    s[t] = sum;
    __syncthreads();
    for (int off = 1; off < 1024; off <<= 1) {
        int v = (t >= off) ? s[t - off] : 0;
        __syncthreads();
        s[t] += v;
        __syncthreads();
    }
    int run = (t == 0) ? 0 : s[t - 1];
    for (int i = start; i < end; i++) {
        g_rowptr[i] = run;
        g_cursor[i] = run;
        run += g_deg[i];
    }
    if (t == 1023) g_rowptr[NN] = s[1023];
}
__global__ void k_scatter(const int* __restrict__ src, const int* __restrict__ dst) {
    int e = blockIdx.x * blockDim.x + threadIdx.x;
    if (e < NE) {
        int d = dst[e];
        int pos = atomicAdd(&g_cursor[d], 1);
        g_col[pos] = src[e];
    }
}

// ---------------- weight transpose: Wt[n*K + k] = W[k*N + n] ----------------
__global__ void k_transpose(const float* __restrict__ W, float* __restrict__ Wt, int K, int N) {
    int idx = blockIdx.x * blockDim.x + threadIdx.x;
    if (idx < K * N) {
        int k = idx / N, n = idx % N;
        Wt[n * K + k] = W[idx];
    }
}

// ---------------- bf16 split helpers ----------------
__device__ __forceinline__ void split2(float a, float b, uint32_t& hi, uint32_t& lo) {
    __nv_bfloat16 ha = __float2bfloat16(a);
    __nv_bfloat16 hb = __float2bfloat16(b);
    __nv_bfloat16 la = __float2bfloat16(a - __bfloat162float(ha));
    __nv_bfloat16 lb = __float2bfloat16(b - __bfloat162float(hb));
    __nv_bfloat162 h2 = __halves2bfloat162(ha, hb);
    __nv_bfloat162 l2 = __halves2bfloat162(la, lb);
    hi = *reinterpret_cast<uint32_t*>(&h2);
    lo = *reinterpret_cast<uint32_t*>(&l2);
}

__device__ __forceinline__ void mma_bf16(float* c, const uint32_t* a, const uint32_t* b) {
    asm volatile("mma.sync.aligned.m16n8k16.row.col.f32.bf16.bf16.f32 "
                 "{%0,%1,%2,%3}, {%4,%5,%6,%7}, {%8,%9}, {%0,%1,%2,%3};"
                 : "+f"(c[0]), "+f"(c[1]), "+f"(c[2]), "+f"(c[3])
                 : "r"(a[0]), "r"(a[1]), "r"(a[2]), "r"(a[3]), "r"(b[0]), "r"(b[1]));
}

// ---------------- mma.sync bf16-split GEMM: C = A[M,K] @ Wt[N,K]^T + bias ----
// CTA tile 128 x NTILE, BK=32. 8 warps in 2(M) x 4(N) grid; warp tile 64 x NTILE/4.
// A,B split to bf16 hi/lo in smem (row stride 40 bf16 -> conflict-free frags).
template <int NTILE>
__global__ void __launch_bounds__(256)
gemm_mma(const float* __restrict__ A, const float* __restrict__ Wt,
         const float* __restrict__ bias, float* __restrict__ C,
         int M, int N, int K) {
    constexpr int STR = 40;            // bf16 elements per smem row (padded)
    constexpr int NT = NTILE / 32;     // n-tiles (of 8) per warp: 4 or 2
    __shared__ __nv_bfloat16 Ah[128 * STR], Al[128 * STR];
    __shared__ __nv_bfloat16 Bh[NTILE * STR], Bl[NTILE * STR];

    const int tid = threadIdx.x;
    const int wid = tid >> 5;
    const int lane = tid & 31;
    const int wm = wid & 1;            // 0..1
    const int wn = wid >> 1;           // 0..3
    const int gid = lane >> 2;         // 0..7
    const int tig = lane & 3;          // 0..3
    const int m0 = blockIdx.y * 128;
    const int n0 = blockIdx.x * NTILE;

    float c[4][NT][4];
#pragma unroll
    for (int mt = 0; mt < 4; mt++)
#pragma unroll
        for (int nt = 0; nt < NT; nt++)
#pragma unroll
            for (int r = 0; r < 4; r++) c[mt][nt][r] = 0.f;

    for (int k0 = 0; k0 < K; k0 += 32) {
        // --- load + split A tile: 128 rows x 32 floats ---
#pragma unroll
        for (int j = 0; j < 4; j++) {
            int i = tid + j * 256;           // float4 index (1024 total)
            int row = i >> 3, c4 = i & 7;
            float4 v = make_float4(0.f, 0.f, 0.f, 0.f);
            int gm = m0 + row;
            if (gm < M) v = *reinterpret_cast<const float4*>(A + (size_t)gm * K + k0 + c4 * 4);
            uint2 h, l;
            split2(v.x, v.y, h.x, l.x);
            split2(v.z, v.w, h.y, l.y);
            int off = row * STR + c4 * 4;
            *reinterpret_cast<uint2*>(&Ah[off]) = h;
            *reinterpret_cast<uint2*>(&Al[off]) = l;
        }
        // --- load + split B tile: NTILE rows x 32 floats ---
#pragma unroll
        for (int j = 0; j < NTILE / 32; j++) {
            int i = tid + j * 256;
            int row = i >> 3, c4 = i & 7;
            float4 v = *reinterpret_cast<const float4*>(Wt + (size_t)(n0 + row) * K + k0 + c4 * 4);
            uint2 h, l;
            split2(v.x, v.y, h.x, l.x);
            split2(v.z, v.w, h.y, l.y);
            int off = row * STR + c4 * 4;
            *reinterpret_cast<uint2*>(&Bh[off]) = h;
            *reinterpret_cast<uint2*>(&Bl[off]) = l;
        }
        __syncthreads();

#pragma unroll
        for (int ks = 0; ks < 2; ks++) {
            const int kb = ks * 16;
            uint32_t afh[4][4], afl[4][4];
#pragma unroll
            for (int mt = 0; mt < 4; mt++) {
                int rb = wm * 64 + mt * 16;
                int o00 = (rb + gid) * STR + kb + tig * 2;
                int o10 = (rb + gid + 8) * STR + kb + tig * 2;
                afh[mt][0] = *reinterpret_cast<const uint32_t*>(&Ah[o00]);
                afh[mt][1] = *reinterpret_cast<const uint32_t*>(&Ah[o10]);
                afh[mt][2] = *reinterpret_cast<const uint32_t*>(&Ah[o00 + 8]);
                afh[mt][3] = *reinterpret_cast<const uint32_t*>(&Ah[o10 + 8]);
                afl[mt][0] = *reinterpret_cast<const uint32_t*>(&Al[o00]);
                afl[mt][1] = *reinterpret_cast<const uint32_t*>(&Al[o10]);
                afl[mt][2] = *reinterpret_cast<const uint32_t*>(&Al[o00 + 8]);
                afl[mt][3] = *reinterpret_cast<const uint32_t*>(&Al[o10 + 8]);
            }
            uint32_t bfh[NT][2], bfl[NT][2];
#pragma unroll
            for (int nt = 0; nt < NT; nt++) {
                int nb = wn * (NT * 8) + nt * 8;
                int o = (nb + gid) * STR + kb + tig * 2;
                bfh[nt][0] = *reinterpret_cast<const uint32_t*>(&Bh[o]);
                bfh[nt][1] = *reinterpret_cast<const uint32_t*>(&Bh[o + 8]);
                bfl[nt][0] = *reinterpret_cast<const uint32_t*>(&Bl[o]);
                bfl[nt][1] = *reinterpret_cast<const uint32_t*>(&Bl[o + 8]);
            }
#pragma unroll
            for (int mt = 0; mt < 4; mt++)
#pragma unroll
                for (int nt = 0; nt < NT; nt++) {
                    mma_bf16(c[mt][nt], afh[mt], bfh[nt]);   // hi*hi
                    mma_bf16(c[mt][nt], afh[mt], bfl[nt]);   // hi*lo
                    mma_bf16(c[mt][nt], afl[mt], bfh[nt]);   // lo*hi
                }
        }
        __syncthreads();
    }

    // epilogue: add bias, store fp32
#pragma unroll
    for (int mt = 0; mt < 4; mt++) {
        int r0 = m0 + wm * 64 + mt * 16 + gid;
#pragma unroll
        for (int nt = 0; nt < NT; nt++) {
            int col = n0 + wn * (NT * 8) + nt * 8 + tig * 2;
            float b0 = bias[col], b1 = bias[col + 1];
            if (r0 < M) {
                float2 v0 = make_float2(c[mt][nt][0] + b0, c[mt][nt][1] + b1);
                *reinterpret_cast<float2*>(C + (size_t)r0 * N + col) = v0;
            }
            if (r0 + 8 < M) {
                float2 v1 = make_float2(c[mt][nt][2] + b0, c[mt][nt][3] + b1);
                *reinterpret_cast<float2*>(C + (size_t)(r0 + 8) * N + col) = v1;
            }
        }
    }
}

// ---------------- fused GATv2 edge-softmax + aggregation ----------------
template <int D>
__global__ void k_agg(const float* __restrict__ xl, const float* __restrict__ xr,
                      const float* __restrict__ att, const float* __restrict__ bias,
                      float* __restrict__ out) {
    constexpr int CPL = D / 32;
    constexpr int V = CPL / 4;

    int warp = (blockIdx.x * blockDim.x + threadIdx.x) >> 5;
    int lane = threadIdx.x & 31;
    if (warp >= NN) return;
    const int node = warp;
    const int base = lane * CPL;

    float attv[CPL], xrv[CPL];
#pragma unroll
    for (int j = 0; j < V; j++) {
        float4 a4 = *reinterpret_cast<const float4*>(att + base + 4 * j);
        float4 r4 = *reinterpret_cast<const float4*>(xr + node * D + base + 4 * j);
        attv[4 * j + 0] = a4.x; attv[4 * j + 1] = a4.y;
        attv[4 * j + 2] = a4.z; attv[4 * j + 3] = a4.w;
        xrv[4 * j + 0] = r4.x; xrv[4 * j + 1] = r4.y;
        xrv[4 * j + 2] = r4.z; xrv[4 * j + 3] = r4.w;
    }

    float m = -3.402823466e38f;
    float ssum = 0.f;
    float acc[CPL];
#pragma unroll
    for (int c = 0; c < CPL; c++) acc[c] = 0.f;

    const int rs = g_rowptr[node];
    const int re = g_rowptr[node + 1];
    for (int p = rs; p < re; p++) {
        int s = g_col[p];
        float xlv[CPL];
#pragma unroll
        for (int j = 0; j < V; j++) {
            float4 v = *reinterpret_cast<const float4*>(xl + s * D + base + 4 * j);
            xlv[4 * j + 0] = v.x; xlv[4 * j + 1] = v.y;
            xlv[4 * j + 2] = v.z; xlv[4 * j + 3] = v.w;
        }
        float partial = 0.f;
#pragma unroll
        for (int c = 0; c < CPL; c++) {
            float e = xlv[c] + xrv[c];
            e = (e >= 0.f) ? e : 0.2f * e;
            partial = fmaf(attv[c], e, partial);
        }
        partial += __shfl_xor_sync(0xffffffffu, partial, 1);
        partial += __shfl_xor_sync(0xffffffffu, partial, 2);
        partial += __shfl_xor_sync(0xffffffffu, partial, 4);

        float mnew = fmaxf(m, partial);
        float fac = __expf(m - mnew);
        float w = __expf(partial - mnew);
        ssum = ssum * fac + w;
#pragma unroll
        for (int c = 0; c < CPL; c++) acc[c] = fmaf(acc[c], fac, w * xlv[c]);
        m = mnew;
    }

    float inv = (ssum > 0.f) ? (1.f / ssum) : 0.f;
#pragma unroll
    for (int c = 0; c < CPL; c++) {
        float v = fmaf(acc[c], inv, bias[base + c]);
        out[node * D + base + c] = fmaxf(v, 0.f);
    }
}

// ---------------- launch ----------------
extern "C" void kernel_launch(void* const* d_in, const int* in_sizes, int n_in,
                              void* d_out, int out_size) {
    (void)in_sizes; (void)n_in; (void)out_size;
    const float* x     = (const float*)d_in[0];
    const int*   ei    = (const int*)  d_in[1];
    const float* Wl1   = (const float*)d_in[3];
    const float* bl1   = (const float*)d_in[4];
    const float* Wr1   = (const float*)d_in[5];
    const float* br1   = (const float*)d_in[6];
    const float* att1  = (const float*)d_in[7];
    const float* bias1 = (const float*)d_in[8];
    const float* Wl2   = (const float*)d_in[9];
    const float* bl2   = (const float*)d_in[10];
    const float* Wr2   = (const float*)d_in[11];
    const float* br2   = (const float*)d_in[12];
    const float* att2  = (const float*)d_in[13];
    const float* bias2 = (const float*)d_in[14];
    const float* Wlin  = (const float*)d_in[15];
    const float* blin  = (const float*)d_in[16];
    float* out = (float*)d_out;

    const int* src = ei;
    const int* dst = ei + NE;

    float *xl1, *xr1, *h1, *xl2, *xr2, *h2;
    float *wl1t, *wr1t, *wl2t, *wr2t, *wlint;
    cudaGetSymbolAddress((void**)&xl1, g_xl1);
    cudaGetSymbolAddress((void**)&xr1, g_xr1);
    cudaGetSymbolAddress((void**)&h1,  g_h1);
    cudaGetSymbolAddress((void**)&xl2, g_xl2);
    cudaGetSymbolAddress((void**)&xr2, g_xr2);
    cudaGetSymbolAddress((void**)&h2,  g_h2);
    cudaGetSymbolAddress((void**)&wl1t, g_wl1t);
    cudaGetSymbolAddress((void**)&wr1t, g_wr1t);
    cudaGetSymbolAddress((void**)&wl2t, g_wl2t);
    cudaGetSymbolAddress((void**)&wr2t, g_wr2t);
    cudaGetSymbolAddress((void**)&wlint, g_wlint);

    // CSR build
    k_zero_deg<<<(NN + 255) / 256, 256>>>();
    k_hist<<<(NE + 255) / 256, 256>>>(dst);
    k_scan<<<1, 1024>>>();
    k_scatter<<<(NE + 255) / 256, 256>>>(src, dst);

    // weight transposes (W[K,N] -> Wt[N,K])
    k_transpose<<<(128 * 128 + 255) / 256, 256>>>(Wl1, wl1t, 128, 128);
    k_transpose<<<(128 * 128 + 255) / 256, 256>>>(Wr1, wr1t, 128, 128);
    k_transpose<<<(128 * 512 + 255) / 256, 256>>>(Wl2, wl2t, 128, 512);
    k_transpose<<<(128 * 512 + 255) / 256, 256>>>(Wr2, wr2t, 128, 512);
    k_transpose<<<(512 * 64 + 255) / 256, 256>>>(Wlin, wlint, 512, 64);

    const int MB = (NN + 127) / 128;  // 157

    // Layer 1 transforms (M=20000, N=128, K=128)
    gemm_mma<128><<<dim3(1, MB), 256>>>(x, wl1t, bl1, xl1, NN, 128, 128);
    gemm_mma<128><<<dim3(1, MB), 256>>>(x, wr1t, br1, xr1, NN, 128, 128);
    k_agg<128><<<NN / 8, 256>>>(xl1, xr1, att1, bias1, h1);

    // Layer 2 transforms (M=20000, N=512, K=128)
    gemm_mma<128><<<dim3(4, MB), 256>>>(h1, wl2t, bl2, xl2, NN, 512, 128);
    gemm_mma<128><<<dim3(4, MB), 256>>>(h1, wr2t, br2, xr2, NN, 512, 128);
    k_agg<512><<<NN / 8, 256>>>(xl2, xr2, att2, bias2, h2);

    // Output linear (M=20000, N=64, K=512)
    gemm_mma<64><<<dim3(1, MB), 256>>>(h2, wlint, blin, out, NN, 64, 512);
}

// round 4
// speedup vs baseline: 1.8592x; 1.0100x over previous
#include <cuda_runtime.h>
#include <cuda_bf16.h>
#include <cstdint>

#define NN 20000
#define NE 160000

// ---------------- scratch (device globals: allocation-free) ----------------
__device__ __nv_bfloat16 g_xhi[NN * 128], g_xlo[NN * 128];
__device__ float g_xlr1[NN * 256];
__device__ __nv_bfloat16 g_h1hi[NN * 128], g_h1lo[NN * 128];
__device__ float g_xlr2[NN * 1024];
__device__ __nv_bfloat16 g_h2hi[NN * 512], g_h2lo[NN * 512];
__device__ __nv_bfloat16 g_wt1hi[256 * 128],  g_wt1lo[256 * 128];
__device__ __nv_bfloat16 g_wt2hi[1024 * 128], g_wt2lo[1024 * 128];
__device__ __nv_bfloat16 g_wtlhi[64 * 512],   g_wtllo[64 * 512];
__device__ int g_deg[NN];
__device__ int g_rowptr[NN + 1];
__device__ int g_cursor[NN];
__device__ int g_col[NE];

// ---------------- helpers ----------------
__device__ __forceinline__ uint32_t smem_u32(const void* p) {
    uint32_t a;
    asm("{ .reg .u64 t; cvta.to.shared.u64 t, %1; cvt.u32.u64 %0, t; }" : "=r"(a) : "l"(p));
    return a;
}
__device__ __forceinline__ void cp_async16(uint32_t dst, const void* src, bool pred) {
    int sz = pred ? 16 : 0;
    asm volatile("cp.async.cg.shared.global [%0], [%1], 16, %2;"
                 :: "r"(dst), "l"(src), "r"(sz) : "memory");
}
__device__ __forceinline__ void cp_commit() {
    asm volatile("cp.async.commit_group;" ::: "memory");
}
template <int W> __device__ __forceinline__ void cp_wait() {
    asm volatile("cp.async.wait_group %0;" :: "n"(W) : "memory");
}
__device__ __forceinline__ void split1(float a, __nv_bfloat16& h, __nv_bfloat16& l) {
    h = __float2bfloat16(a);
    l = __float2bfloat16(a - __bfloat162float(h));
}
__device__ __forceinline__ void mma_bf16(float* c, const uint32_t* a, const uint32_t* b) {
    asm volatile("mma.sync.aligned.m16n8k16.row.col.f32.bf16.bf16.f32 "
                 "{%0,%1,%2,%3}, {%4,%5,%6,%7}, {%8,%9}, {%0,%1,%2,%3};"
                 : "+f"(c[0]), "+f"(c[1]), "+f"(c[2]), "+f"(c[3])
                 : "r"(a[0]), "r"(a[1]), "r"(a[2]), "r"(a[3]), "r"(b[0]), "r"(b[1]));
}

// ---------------- CSR build (counting sort by dst) ----------------
__global__ void k_zero_deg() {
    int i = blockIdx.x * blockDim.x + threadIdx.x;
    if (i < NN) g_deg[i] = 0;
}
__global__ void k_hist(const int* __restrict__ dst) {
    int e = blockIdx.x * blockDim.x + threadIdx.x;
    if (e < NE) atomicAdd(&g_deg[dst[e]], 1);
}
__global__ void k_scan() {
    __shared__ int s[1024];
    const int CH = (NN + 1023) / 1024;
    int t = threadIdx.x;
    int start = t * CH;
    int end = start + CH < NN ? start + CH : NN;
    int sum = 0;
    for (int i = start; i < end; i++) sum += g_deg[i];
    s[t] = sum;
    __syncthreads();
    for (int off = 1; off < 1024; off <<= 1) {
        int v = (t >= off) ? s[t - off] : 0;
        __syncthreads();
        s[t] += v;
        __syncthreads();
    }
    int run = (t == 0) ? 0 : s[t - 1];
    for (int i = start; i < end; i++) {
        g_rowptr[i] = run;
        g_cursor[i] = run;
        run += g_deg[i];
    }
    if (t == 1023) g_rowptr[NN] = s[1023];
}
__global__ void k_scatter(const int* __restrict__ src, const int* __restrict__ dst) {
    int e = blockIdx.x * blockDim.x + threadIdx.x;
    if (e < NE) {
        int d = dst[e];
        int pos = atomicAdd(&g_cursor[d], 1);
        g_col[pos] = src[e];
    }
}

// ---------------- x split: fp32 -> bf16 hi/lo ----------------
__global__ void k_split(const float* __restrict__ X, __nv_bfloat16* __restrict__ hi,
                        __nv_bfloat16* __restrict__ lo, int n) {
    int i = blockIdx.x * blockDim.x + threadIdx.x;
    if (i < n) {
        __nv_bfloat16 h, l;
        split1(X[i], h, l);
        hi[i] = h; lo[i] = l;
    }
}

// ---------------- weight transpose + split: Wt[n*K+k] = split(W[k*N+n]) ------
__global__ void k_tsplit(const float* __restrict__ W, __nv_bfloat16* __restrict__ Whi,
                         __nv_bfloat16* __restrict__ Wlo, int K, int N) {
    int idx = blockIdx.x * blockDim.x + threadIdx.x;
    if (idx < K * N) {
        int k = idx / N, n = idx % N;
        __nv_bfloat16 h, l;
        split1(W[idx], h, l);
        Whi[n * K + k] = h;
        Wlo[n * K + k] = l;
    }
}

// ---------------- pipelined bf16-split GEMM -------------------------------
// C[M,N] = (Ahi+Alo)[M,K] @ (Bhi+Blo)[N,K]^T + bias, fp32 accumulate.
// CTA tile 128 x BN, BK=64, 2-stage cp.async pipeline, 8 warps (2M x 4N).
template <int BN>
__global__ void __launch_bounds__(256)
gemm_bf16(const __nv_bfloat16* __restrict__ Ahi, const __nv_bfloat16* __restrict__ Alo,
          const __nv_bfloat16* __restrict__ Bhi, const __nv_bfloat16* __restrict__ Blo,
          const float* __restrict__ bias, float* __restrict__ C,
          int M, int N, int K) {
    constexpr int BK = 64;
    constexpr int STR = 72;                 // padded row (bf16 elems), conflict-free
    constexpr int ASZ = 128 * STR;          // elems
    constexpr int BSZ = BN * STR;
    constexpr int STAGE = 2 * ASZ + 2 * BSZ;
    constexpr int NT = BN / 32;             // 8-col tiles per warp
    extern __shared__ __nv_bfloat16 sm[];

    const int tid = threadIdx.x;
    const int wid = tid >> 5;
    const int lane = tid & 31;
    const int wm = wid & 1;
    const int wn = wid >> 1;
    const int gid = lane >> 2;
    const int tig = lane & 3;
    const int m0 = blockIdx.y * 128;
    const int n0 = blockIdx.x * BN;
    const int nk = K / BK;

    float c[4][NT][4];
#pragma unroll
    for (int mt = 0; mt < 4; mt++)
#pragma unroll
        for (int nt = 0; nt < NT; nt++)
#pragma unroll
            for (int r = 0; r < 4; r++) c[mt][nt][r] = 0.f;

    auto load_stage = [&](int kc, int s) {
        const int k0 = kc * BK;
        __nv_bfloat16* base = sm + s * STAGE;
        // A hi/lo: 128 rows x 8 chunks (16B) each
#pragma unroll
        for (int j = 0; j < 4; j++) {
            int i = tid + j * 256;
            int row = i >> 3, ch = i & 7;
            int gm = m0 + row;
            bool p = gm < M;
            int gmc = p ? gm : (M - 1);
            size_t goff = (size_t)gmc * K + k0 + ch * 8;
            uint32_t d = smem_u32(base + row * STR + ch * 8);
            cp_async16(d, Ahi + goff, p);
            cp_async16(d + ASZ * 2, Alo + goff, p);
        }
        // B hi/lo: BN rows x 8 chunks each (always in bounds)
#pragma unroll
        for (int j = 0; j < BN / 32; j++) {
            int i = tid + j * 256;
            int row = i >> 3, ch = i & 7;
            size_t goff = (size_t)(n0 + row) * K + k0 + ch * 8;
            uint32_t d = smem_u32(base + 2 * ASZ + row * STR + ch * 8);
            cp_async16(d, Bhi + goff, true);
            cp_async16(d + BSZ * 2, Blo + goff, true);
        }
    };

    load_stage(0, 0);
    cp_commit();

    for (int kc = 0; kc < nk; kc++) {
        const int s = kc & 1;
        if (kc + 1 < nk) {
            load_stage(kc + 1, s ^ 1);
            cp_commit();
            cp_wait<1>();
        } else {
            cp_wait<0>();
        }
        __syncthreads();

        const __nv_bfloat16* Ah = sm + s * STAGE;
        const __nv_bfloat16* Al = Ah + ASZ;
        const __nv_bfloat16* Bh = Al + ASZ;
        const __nv_bfloat16* Bl = Bh + BSZ;

#pragma unroll
        for (int kb = 0; kb < BK; kb += 16) {
            uint32_t afh[4][4], afl[4][4];
#pragma unroll
            for (int mt = 0; mt < 4; mt++) {
                int rb = wm * 64 + mt * 16;
                int o00 = (rb + gid) * STR + kb + tig * 2;
                int o10 = (rb + gid + 8) * STR + kb + tig * 2;
                afh[mt][0] = *reinterpret_cast<const uint32_t*>(&Ah[o00]);
                afh[mt][1] = *reinterpret_cast<const uint32_t*>(&Ah[o10]);
                afh[mt][2] = *reinterpret_cast<const uint32_t*>(&Ah[o00 + 8]);
                afh[mt][3] = *reinterpret_cast<const uint32_t*>(&Ah[o10 + 8]);
                afl[mt][0] = *reinterpret_cast<const uint32_t*>(&Al[o00]);
                afl[mt][1] = *reinterpret_cast<const uint32_t*>(&Al[o10]);
                afl[mt][2] = *reinterpret_cast<const uint32_t*>(&Al[o00 + 8]);
                afl[mt][3] = *reinterpret_cast<const uint32_t*>(&Al[o10 + 8]);
            }
            uint32_t bfh[NT][2], bfl[NT][2];
#pragma unroll
            for (int nt = 0; nt < NT; nt++) {
                int nb = wn * (NT * 8) + nt * 8;
                int o = (nb + gid) * STR + kb + tig * 2;
                bfh[nt][0] = *reinterpret_cast<const uint32_t*>(&Bh[o]);
                bfh[nt][1] = *reinterpret_cast<const uint32_t*>(&Bh[o + 8]);
                bfl[nt][0] = *reinterpret_cast<const uint32_t*>(&Bl[o]);
                bfl[nt][1] = *reinterpret_cast<const uint32_t*>(&Bl[o + 8]);
            }
#pragma unroll
            for (int mt = 0; mt < 4; mt++)
#pragma unroll
                for (int nt = 0; nt < NT; nt++) {
                    mma_bf16(c[mt][nt], afh[mt], bfh[nt]);   // hi*hi
                    mma_bf16(c[mt][nt], afh[mt], bfl[nt]);   // hi*lo
                    mma_bf16(c[mt][nt], afl[mt], bfh[nt]);   // lo*hi
                }
        }
        __syncthreads();
    }

    // epilogue: add bias, store fp32
#pragma unroll
    for (int mt = 0; mt < 4; mt++) {
        int r0 = m0 + wm * 64 + mt * 16 + gid;
#pragma unroll
        for (int nt = 0; nt < NT; nt++) {
            int col = n0 + wn * (NT * 8) + nt * 8 + tig * 2;
            float b0 = bias[col], b1 = bias[col + 1];
            if (r0 < M) {
                float2 v0 = make_float2(c[mt][nt][0] + b0, c[mt][nt][1] + b1);
                *reinterpret_cast<float2*>(C + (size_t)r0 * N + col) = v0;
            }
            if (r0 + 8 < M) {
                float2 v1 = make_float2(c[mt][nt][2] + b0, c[mt][nt][3] + b1);
                *reinterpret_cast<float2*>(C + (size_t)(r0 + 8) * N + col) = v1;
            }
        }
    }
}

// ---------------- fused GATv2 edge-softmax + aggregation ----------------
// Reads xl/xr from combined xlr buffer (row stride SR floats, xr at +XO).
// Writes relu(agg + bias) split to bf16 hi/lo (feeds next GEMM).
template <int D>
__global__ void k_agg(const float* __restrict__ xlr, int SR, int XO,
                      const float* __restrict__ att, const float* __restrict__ bias,
                      __nv_bfloat16* __restrict__ ohi, __nv_bfloat16* __restrict__ olo) {
    constexpr int CPL = D / 32;
    constexpr int V = CPL / 4;

    int warp = (blockIdx.x * blockDim.x + threadIdx.x) >> 5;
    int lane = threadIdx.x & 31;
    if (warp >= NN) return;
    const int node = warp;
    const int base = lane * CPL;

    float attv[CPL], xrv[CPL];
#pragma unroll
    for (int j = 0; j < V; j++) {
        float4 a4 = *reinterpret_cast<const float4*>(att + base + 4 * j);
        float4 r4 = *reinterpret_cast<const float4*>(xlr + (size_t)node * SR + XO + base + 4 * j);
        attv[4 * j + 0] = a4.x; attv[4 * j + 1] = a4.y;
        attv[4 * j + 2] = a4.z; attv[4 * j + 3] = a4.w;
        xrv[4 * j + 0] = r4.x; xrv[4 * j + 1] = r4.y;
        xrv[4 * j + 2] = r4.z; xrv[4 * j + 3] = r4.w;
    }

    float m = -3.402823466e38f;
    float ssum = 0.f;
    float acc[CPL];
#pragma unroll
    for (int c = 0; c < CPL; c++) acc[c] = 0.f;

    const int rs = g_rowptr[node];
    const int re = g_rowptr[node + 1];
    for (int p = rs; p < re; p++) {
        int s = g_col[p];
        float xlv[CPL];
#pragma unroll
        for (int j = 0; j < V; j++) {
            float4 v = *reinterpret_cast<const float4*>(xlr + (size_t)s * SR + base + 4 * j);
            xlv[4 * j + 0] = v.x; xlv[4 * j + 1] = v.y;
            xlv[4 * j + 2] = v.z; xlv[4 * j + 3] = v.w;
        }
        float partial = 0.f;
#pragma unroll
        for (int c = 0; c < CPL; c++) {
            float e = xlv[c] + xrv[c];
            e = (e >= 0.f) ? e : 0.2f * e;
            partial = fmaf(attv[c], e, partial);
        }
        partial += __shfl_xor_sync(0xffffffffu, partial, 1);
        partial += __shfl_xor_sync(0xffffffffu, partial, 2);
        partial += __shfl_xor_sync(0xffffffffu, partial, 4);

        float mnew = fmaxf(m, partial);
        float fac = __expf(m - mnew);
        float w = __expf(partial - mnew);
        ssum = ssum * fac + w;
#pragma unroll
        for (int c = 0; c < CPL; c++) acc[c] = fmaf(acc[c], fac, w * xlv[c]);
        m = mnew;
    }

    float inv = (ssum > 0.f) ? (1.f / ssum) : 0.f;
#pragma unroll
    for (int j = 0; j < CPL / 2; j++) {
        float v0 = fmaxf(fmaf(acc[2 * j], inv, bias[base + 2 * j]), 0.f);
        float v1 = fmaxf(fmaf(acc[2 * j + 1], inv, bias[base + 2 * j + 1]), 0.f);
        __nv_bfloat16 h0, l0, h1, l1;
        split1(v0, h0, l0);
        split1(v1, h1, l1);
        __nv_bfloat162 hp = __halves2bfloat162(h0, h1);
        __nv_bfloat162 lp = __halves2bfloat162(l0, l1);
        *reinterpret_cast<__nv_bfloat162*>(ohi + (size_t)node * D + base + 2 * j) = hp;
        *reinterpret_cast<__nv_bfloat162*>(olo + (size_t)node * D + base + 2 * j) = lp;
    }
}

// ---------------- launch ----------------
extern "C" void kernel_launch(void* const* d_in, const int* in_sizes, int n_in,
                              void* d_out, int out_size) {
    (void)in_sizes; (void)n_in; (void)out_size;
    const float* x     = (const float*)d_in[0];
    const int*   ei    = (const int*)  d_in[1];
    const float* Wl1   = (const float*)d_in[3];
    const float* bl1   = (const float*)d_in[4];
    const float* Wr1   = (const float*)d_in[5];
    const float* br1   = (const float*)d_in[6];
    const float* att1  = (const float*)d_in[7];
    const float* bias1 = (const float*)d_in[8];
    const float* Wl2   = (const float*)d_in[9];
    const float* bl2   = (const float*)d_in[10];
    const float* Wr2   = (const float*)d_in[11];
    const float* br2   = (const float*)d_in[12];
    const float* att2  = (const float*)d_in[13];
    const float* bias2 = (const float*)d_in[14];
    const float* Wlin  = (const float*)d_in[15];
    const float* blin  = (const float*)d_in[16];
    float* out = (float*)d_out;

    const int* src = ei;
    const int* dst = ei + NE;

    __nv_bfloat16 *xhi, *xlo, *h1hi, *h1lo, *h2hi, *h2lo;
    __nv_bfloat16 *wt1hi, *wt1lo, *wt2hi, *wt2lo, *wtlhi, *wtllo;
    float *xlr1, *xlr2;
    cudaGetSymbolAddress((void**)&xhi, g_xhi);
    cudaGetSymbolAddress((void**)&xlo, g_xlo);
    cudaGetSymbolAddress((void**)&h1hi, g_h1hi);
    cudaGetSymbolAddress((void**)&h1lo, g_h1lo);
    cudaGetSymbolAddress((void**)&h2hi, g_h2hi);
    cudaGetSymbolAddress((void**)&h2lo, g_h2lo);
    cudaGetSymbolAddress((void**)&wt1hi, g_wt1hi);
    cudaGetSymbolAddress((void**)&wt1lo, g_wt1lo);
    cudaGetSymbolAddress((void**)&wt2hi, g_wt2hi);
    cudaGetSymbolAddress((void**)&wt2lo, g_wt2lo);
    cudaGetSymbolAddress((void**)&wtlhi, g_wtlhi);
    cudaGetSymbolAddress((void**)&wtllo, g_wtllo);
    cudaGetSymbolAddress((void**)&xlr1, g_xlr1);
    cudaGetSymbolAddress((void**)&xlr2, g_xlr2);

    static bool attr_done = false;
    if (!attr_done) {
        cudaFuncSetAttribute(gemm_bf16<128>, cudaFuncAttributeMaxDynamicSharedMemorySize, 160 * 1024);
        cudaFuncSetAttribute(gemm_bf16<64>,  cudaFuncAttributeMaxDynamicSharedMemorySize, 120 * 1024);
        attr_done = true;
    }

    // CSR build
    k_zero_deg<<<(NN + 255) / 256, 256>>>();
    k_hist<<<(NE + 255) / 256, 256>>>(dst);
    k_scan<<<1, 1024>>>();
    k_scatter<<<(NE + 255) / 256, 256>>>(src, dst);

    // input split + weight transpose/split (l and r concatenated along N)
    k_split<<<(NN * 128 + 255) / 256, 256>>>(x, xhi, xlo, NN * 128);
    k_tsplit<<<(128 * 128 + 255) / 256, 256>>>(Wl1, wt1hi, wt1lo, 128, 128);
    k_tsplit<<<(128 * 128 + 255) / 256, 256>>>(Wr1, wt1hi + 128 * 128, wt1lo + 128 * 128, 128, 128);
    k_tsplit<<<(128 * 512 + 255) / 256, 256>>>(Wl2, wt2hi, wt2lo, 128, 512);
    k_tsplit<<<(128 * 512 + 255) / 256, 256>>>(Wr2, wt2hi + 512 * 128, wt2lo + 512 * 128, 128, 512);
    k_tsplit<<<(512 * 64 + 255) / 256, 256>>>(Wlin, wtlhi, wtllo, 512, 64);

    const int MB = (NN + 127) / 128;  // 157
    constexpr int SMEM128 = 2 * (2 * 128 * 72 + 2 * 128 * 72) * 2;  // 147456 B
    constexpr int SMEM64  = 2 * (2 * 128 * 72 + 2 * 64 * 72) * 2;   // 110592 B

    // combined bias buffers live at the front of xlr scratch? No — biases are
    // separate inputs; pass per-half via two GEMM col ranges using bias concat:
    // simpler: bl/br are distinct arrays; build concatenated bias on the fly is
    // avoided by noting gemm needs bias[n0+col]: we pass the l-bias for block 0
    // and r-bias for block 1 via a per-launch trick: bias pointer contiguity.
    // Here bl1,br1 etc. are separate allocations, so launch per half-range:
    // Layer 1: single A pass is kept by launching one GEMM per weight half.
    gemm_bf16<128><<<dim3(1, MB), 256, SMEM128>>>(xhi, xlo, wt1hi, wt1lo, bl1, xlr1 + 0, NN, 256, 128);
    gemm_bf16<128><<<dim3(1, MB), 256, SMEM128>>>(xhi, xlo, wt1hi + 128 * 128, wt1lo + 128 * 128, br1, xlr1 + 128, NN, 256, 128);
    k_agg<128><<<NN / 8, 256>>>(xlr1, 256, 128, att1, bias1, h1hi, h1lo);

    gemm_bf16<128><<<dim3(4, MB), 256, SMEM128>>>(h1hi, h1lo, wt2hi, wt2lo, bl2, xlr2 + 0, NN, 1024, 128);
    gemm_bf16<128><<<dim3(4, MB), 256, SMEM128>>>(h1hi, h1lo, wt2hi + 512 * 128, wt2lo + 512 * 128, br2, xlr2 + 512, NN, 1024, 128);
    k_agg<512><<<NN / 8, 256>>>(xlr2, 1024, 512, att2, bias2, h2hi, h2lo);

    gemm_bf16<64><<<dim3(1, MB), 256, SMEM64>>>(h2hi, h2lo, wtlhi, wtllo, blin, out, NN, 64, 512);
}

// round 5
// speedup vs baseline: 1.8793x; 1.0108x over previous
#include <cuda_runtime.h>
#include <cuda_bf16.h>
#include <cstdint>

#define NN 20000
#define NE 160000

// ---------------- scratch (device globals: allocation-free) ----------------
__device__ __nv_bfloat16 g_xhi[NN * 128], g_xlo[NN * 128];
__device__ float g_xlr1[NN * 256];
__device__ __nv_bfloat16 g_h1hi[NN * 128], g_h1lo[NN * 128];
__device__ float g_xlr2[NN * 1024];
__device__ __nv_bfloat16 g_h2hi[NN * 512], g_h2lo[NN * 512];
__device__ __nv_bfloat16 g_wt1hi[256 * 128],  g_wt1lo[256 * 128];
__device__ __nv_bfloat16 g_wt2hi[1024 * 128], g_wt2lo[1024 * 128];
__device__ __nv_bfloat16 g_wtlhi[64 * 512],   g_wtllo[64 * 512];
__device__ float g_cb1[256];
__device__ float g_cb2[1024];
__device__ int g_deg[NN];
__device__ int g_rowptr[NN + 1];
__device__ int g_cursor[NN];
__device__ int g_col[NE];

// ---------------- helpers ----------------
__device__ __forceinline__ uint32_t smem_u32(const void* p) {
    uint32_t a;
    asm("{ .reg .u64 t; cvta.to.shared.u64 t, %1; cvt.u32.u64 %0, t; }" : "=r"(a) : "l"(p));
    return a;
}
__device__ __forceinline__ void cp_async16(uint32_t dst, const void* src, bool pred) {
    int sz = pred ? 16 : 0;
    asm volatile("cp.async.cg.shared.global [%0], [%1], 16, %2;"
                 :: "r"(dst), "l"(src), "r"(sz) : "memory");
}
__device__ __forceinline__ void cp_commit() {
    asm volatile("cp.async.commit_group;" ::: "memory");
}
template <int W> __device__ __forceinline__ void cp_wait() {
    asm volatile("cp.async.wait_group %0;" :: "n"(W) : "memory");
}
__device__ __forceinline__ void split1(float a, __nv_bfloat16& h, __nv_bfloat16& l) {
    h = __float2bfloat16(a);
    l = __float2bfloat16(a - __bfloat162float(h));
}
__device__ __forceinline__ void mma_bf16(float* c, const uint32_t* a, const uint32_t* b) {
    asm volatile("mma.sync.aligned.m16n8k16.row.col.f32.bf16.bf16.f32 "
                 "{%0,%1,%2,%3}, {%4,%5,%6,%7}, {%8,%9}, {%0,%1,%2,%3};"
                 : "+f"(c[0]), "+f"(c[1]), "+f"(c[2]), "+f"(c[3])
                 : "r"(a[0]), "r"(a[1]), "r"(a[2]), "r"(a[3]), "r"(b[0]), "r"(b[1]));
}
__device__ __forceinline__ void ldsm_x4(uint32_t* r, uint32_t addr) {
    asm volatile("ldmatrix.sync.aligned.m8n8.x4.shared.b16 {%0,%1,%2,%3}, [%4];"
                 : "=r"(r[0]), "=r"(r[1]), "=r"(r[2]), "=r"(r[3]) : "r"(addr));
}

// ---------------- CSR build (counting sort by dst) ----------------
__global__ void k_zero_deg() {
    int i = blockIdx.x * blockDim.x + threadIdx.x;
    if (i < NN) g_deg[i] = 0;
}
__global__ void k_hist(const int* __restrict__ dst) {
    int e = blockIdx.x * blockDim.x + threadIdx.x;
    if (e < NE) atomicAdd(&g_deg[dst[e]], 1);
}
__global__ void k_scan() {
    __shared__ int s[1024];
    const int CH = (NN + 1023) / 1024;
    int t = threadIdx.x;
    int start = t * CH;
    int end = start + CH < NN ? start + CH : NN;
    int sum = 0;
    for (int i = start; i < end; i++) sum += g_deg[i];
    s[t] = sum;
    __syncthreads();
    for (int off = 1; off < 1024; off <<= 1) {
        int v = (t >= off) ? s[t - off] : 0;
        __syncthreads();
        s[t] += v;
        __syncthreads();
    }
    int run = (t == 0) ? 0 : s[t - 1];
    for (int i = start; i < end; i++) {
        g_rowptr[i] = run;
        g_cursor[i] = run;
        run += g_deg[i];
    }
    if (t == 1023) g_rowptr[NN] = s[1023];
}
__global__ void k_scatter(const int* __restrict__ src, const int* __restrict__ dst) {
    int e = blockIdx.x * blockDim.x + threadIdx.x;
    if (e < NE) {
        int d = dst[e];
        int pos = atomicAdd(&g_cursor[d], 1);
        g_col[pos] = src[e];
    }
}

// ---------------- x split: fp32 -> bf16 hi/lo ----------------
__global__ void k_split(const float* __restrict__ X, __nv_bfloat16* __restrict__ hi,
                        __nv_bfloat16* __restrict__ lo, int n) {
    int i = blockIdx.x * blockDim.x + threadIdx.x;
    if (i < n) {
        __nv_bfloat16 h, l;
        split1(X[i], h, l);
        hi[i] = h; lo[i] = l;
    }
}

// ---------------- weight transpose + split ----------------
__global__ void k_tsplit(const float* __restrict__ W, __nv_bfloat16* __restrict__ Whi,
                         __nv_bfloat16* __restrict__ Wlo, int K, int N) {
    int idx = blockIdx.x * blockDim.x + threadIdx.x;
    if (idx < K * N) {
        int k = idx / N, n = idx % N;
        __nv_bfloat16 h, l;
        split1(W[idx], h, l);
        Whi[n * K + k] = h;
        Wlo[n * K + k] = l;
    }
}

// ---------------- bias concat ----------------
__global__ void k_bias(const float* __restrict__ bl1, const float* __restrict__ br1,
                       const float* __restrict__ bl2, const float* __restrict__ br2) {
    int i = threadIdx.x + blockIdx.x * blockDim.x;
    if (i < 256) g_cb1[i] = (i < 128) ? bl1[i] : br1[i - 128];
    if (i < 1024) g_cb2[i] = (i < 512) ? bl2[i] : br2[i - 512];
}

// ---------------- pipelined bf16-split GEMM (ldmatrix + mma.sync) ---------
// C[M,N] = (Ahi+Alo)[M,K] @ (Bhi+Blo)[N,K]^T + bias. CTA tile 128 x BN,
// BK=32, 2-stage cp.async. 8 warps (2M x 4N); warp tile 64 x BN/4.
template <int BN>
__global__ void __launch_bounds__(256)
gemm_bf16(const __nv_bfloat16* __restrict__ Ahi, const __nv_bfloat16* __restrict__ Alo,
          const __nv_bfloat16* __restrict__ Bhi, const __nv_bfloat16* __restrict__ Blo,
          const float* __restrict__ bias, float* __restrict__ C,
          int M, int N, int K) {
    constexpr int BK = 32;
    constexpr int STR = 40;                 // padded row (bf16), conflict-free
    constexpr int ASZ = 128 * STR;
    constexpr int BSZ = BN * STR;
    constexpr int STAGE = 2 * ASZ + 2 * BSZ;
    constexpr int NT = BN / 32;             // 8-col tiles per warp (4 or 2)
    extern __shared__ __nv_bfloat16 sm[];

    const int tid = threadIdx.x;
    const int wid = tid >> 5;
    const int lane = tid & 31;
    const int wm = wid & 1;
    const int wn = wid >> 1;
    const int gid = lane >> 2;
    const int tig = lane & 3;
    const int m0 = blockIdx.y * 128;
    const int n0 = blockIdx.x * BN;
    const int nk = K / BK;

    // per-lane ldmatrix base offsets (elems)
    const int a_row = wm * 64 + (lane & 7) + ((lane >> 3) & 1) * 8;
    const int a_koff = (lane & 16) >> 1;        // 0 or 8
    const int b_row = wn * (NT * 8) + (lane & 7) + ((lane & 16) >> 1);
    const int b_koff = lane & 8;                // 0 or 8

    float c[4][NT][4];
#pragma unroll
    for (int mt = 0; mt < 4; mt++)
#pragma unroll
        for (int nt = 0; nt < NT; nt++)
#pragma unroll
            for (int r = 0; r < 4; r++) c[mt][nt][r] = 0.f;

    auto load_stage = [&](int kc, int s) {
        const int k0 = kc * BK;
        __nv_bfloat16* base = sm + s * STAGE;
        // A hi/lo: 128 rows x 4 chunks (16B)
#pragma unroll
        for (int j = 0; j < 2; j++) {
            int i = tid + j * 256;
            int row = i >> 2, ch = i & 3;
            int gm = m0 + row;
            bool p = gm < M;
            int gmc = p ? gm : (M - 1);
            size_t goff = (size_t)gmc * K + k0 + ch * 8;
            uint32_t d = smem_u32(base + row * STR + ch * 8);
            cp_async16(d, Ahi + goff, p);
            cp_async16(d + ASZ * 2, Alo + goff, p);
        }
        // B hi/lo: BN rows x 4 chunks
#pragma unroll
        for (int j = 0; j < BN / 64; j++) {
            int i = tid + j * 256;
            int row = i >> 2, ch = i & 3;
            size_t goff = (size_t)(n0 + row) * K + k0 + ch * 8;
            uint32_t d = smem_u32(base + 2 * ASZ + row * STR + ch * 8);
            cp_async16(d, Bhi + goff, true);
            cp_async16(d + BSZ * 2, Blo + goff, true);
        }
    };

    load_stage(0, 0);
    cp_commit();

    for (int kc = 0; kc < nk; kc++) {
        const int s = kc & 1;
        if (kc + 1 < nk) {
            load_stage(kc + 1, s ^ 1);
            cp_commit();
            cp_wait<1>();
        } else {
            cp_wait<0>();
        }
        __syncthreads();

        const uint32_t stg = smem_u32(sm + s * STAGE);
        const uint32_t ah_base = stg + (a_row * STR + a_koff) * 2;
        const uint32_t al_base = ah_base + ASZ * 2;
        const uint32_t bh_base = stg + 2 * ASZ * 2 + (b_row * STR + b_koff) * 2;
        const uint32_t bl_base = bh_base + BSZ * 2;

#pragma unroll
        for (int kb = 0; kb < BK; kb += 16) {
            // B fragments: one x4 per nt-pair, hi and lo
            uint32_t bfh[NT][2], bfl[NT][2];
#pragma unroll
            for (int p = 0; p < NT / 2; p++) {
                uint32_t off = (p * 16 * STR + kb) * 2;
                ldsm_x4(&bfh[2 * p][0], bh_base + off);   // fills bfh[2p][0..1], bfh[2p+1][0..1]
                ldsm_x4(&bfl[2 * p][0], bl_base + off);
            }
#pragma unroll
            for (int mt = 0; mt < 4; mt++) {
                uint32_t afh[4], afl[4];
                uint32_t off = (mt * 16 * STR + kb) * 2;
                ldsm_x4(afh, ah_base + off);
                ldsm_x4(afl, al_base + off);
#pragma unroll
                for (int nt = 0; nt < NT; nt++) {
                    mma_bf16(c[mt][nt], afh, bfh[nt]);   // hi*hi
                    mma_bf16(c[mt][nt], afh, bfl[nt]);   // hi*lo
                    mma_bf16(c[mt][nt], afl, bfh[nt]);   // lo*hi
                }
            }
        }
        __syncthreads();
    }

    // epilogue: add bias, store fp32
#pragma unroll
    for (int mt = 0; mt < 4; mt++) {
        int r0 = m0 + wm * 64 + mt * 16 + gid;
#pragma unroll
        for (int nt = 0; nt < NT; nt++) {
            int col = n0 + wn * (NT * 8) + nt * 8 + tig * 2;
            float b0 = bias[col], b1 = bias[col + 1];
            if (r0 < M) {
                float2 v0 = make_float2(c[mt][nt][0] + b0, c[mt][nt][1] + b1);
                *reinterpret_cast<float2*>(C + (size_t)r0 * N + col) = v0;
            }
            if (r0 + 8 < M) {
                float2 v1 = make_float2(c[mt][nt][2] + b0, c[mt][nt][3] + b1);
                *reinterpret_cast<float2*>(C + (size_t)(r0 + 8) * N + col) = v1;
            }
        }
    }
}

// ---------------- fused GATv2 edge-softmax + aggregation ----------------
template <int D>
__global__ void k_agg(const float* __restrict__ xlr, int SR, int XO,
                      const float* __restrict__ att, const float* __restrict__ bias,
                      __nv_bfloat16* __restrict__ ohi, __nv_bfloat16* __restrict__ olo) {
    constexpr int CPL = D / 32;
    constexpr int V = CPL / 4;

    int warp = (blockIdx.x * blockDim.x + threadIdx.x) >> 5;
    int lane = threadIdx.x & 31;
    if (warp >= NN) return;
    const int node = warp;
    const int base = lane * CPL;

    float attv[CPL], xrv[CPL];
#pragma unroll
    for (int j = 0; j < V; j++) {
        float4 a4 = *reinterpret_cast<const float4*>(att + base + 4 * j);
        float4 r4 = *reinterpret_cast<const float4*>(xlr + (size_t)node * SR + XO + base + 4 * j);
        attv[4 * j + 0] = a4.x; attv[4 * j + 1] = a4.y;
        attv[4 * j + 2] = a4.z; attv[4 * j + 3] = a4.w;
        xrv[4 * j + 0] = r4.x; xrv[4 * j + 1] = r4.y;
        xrv[4 * j + 2] = r4.z; xrv[4 * j + 3] = r4.w;
    }

    float m = -3.402823466e38f;
    float ssum = 0.f;
    float acc[CPL];
#pragma unroll
    for (int c = 0; c < CPL; c++) acc[c] = 0.f;

    const int rs = g_rowptr[node];
    const int re = g_rowptr[node + 1];
    for (int p = rs; p < re; p++) {
        int s = g_col[p];
        float xlv[CPL];
#pragma unroll
        for (int j = 0; j < V; j++) {
            float4 v = *reinterpret_cast<const float4*>(xlr + (size_t)s * SR + base + 4 * j);
            xlv[4 * j + 0] = v.x; xlv[4 * j + 1] = v.y;
            xlv[4 * j + 2] = v.z; xlv[4 * j + 3] = v.w;
        }
        float partial = 0.f;
#pragma unroll
        for (int c = 0; c < CPL; c++) {
            float e = xlv[c] + xrv[c];
            e = (e >= 0.f) ? e : 0.2f * e;
            partial = fmaf(attv[c], e, partial);
        }
        partial += __shfl_xor_sync(0xffffffffu, partial, 1);
        partial += __shfl_xor_sync(0xffffffffu, partial, 2);
        partial += __shfl_xor_sync(0xffffffffu, partial, 4);

        float mnew = fmaxf(m, partial);
        float fac = __expf(m - mnew);
        float w = __expf(partial - mnew);
        ssum = ssum * fac + w;
#pragma unroll
        for (int c = 0; c < CPL; c++) acc[c] = fmaf(acc[c], fac, w * xlv[c]);
        m = mnew;
    }

    float inv = (ssum > 0.f) ? (1.f / ssum) : 0.f;
#pragma unroll
    for (int j = 0; j < CPL / 2; j++) {
        float v0 = fmaxf(fmaf(acc[2 * j], inv, bias[base + 2 * j]), 0.f);
        float v1 = fmaxf(fmaf(acc[2 * j + 1], inv, bias[base + 2 * j + 1]), 0.f);
        __nv_bfloat16 h0, l0, h1, l1;
        split1(v0, h0, l0);
        split1(v1, h1, l1);
        __nv_bfloat162 hp = __halves2bfloat162(h0, h1);
        __nv_bfloat162 lp = __halves2bfloat162(l0, l1);
        *reinterpret_cast<__nv_bfloat162*>(ohi + (size_t)node * D + base + 2 * j) = hp;
        *reinterpret_cast<__nv_bfloat162*>(olo + (size_t)node * D + base + 2 * j) = lp;
    }
}

// ---------------- launch ----------------
extern "C" void kernel_launch(void* const* d_in, const int* in_sizes, int n_in,
                              void* d_out, int out_size) {
    (void)in_sizes; (void)n_in; (void)out_size;
    const float* x     = (const float*)d_in[0];
    const int*   ei    = (const int*)  d_in[1];
    const float* Wl1   = (const float*)d_in[3];
    const float* bl1   = (const float*)d_in[4];
    const float* Wr1   = (const float*)d_in[5];
    const float* br1   = (const float*)d_in[6];
    const float* att1  = (const float*)d_in[7];
    const float* bias1 = (const float*)d_in[8];
    const float* Wl2   = (const float*)d_in[9];
    const float* bl2   = (const float*)d_in[10];
    const float* Wr2   = (const float*)d_in[11];
    const float* br2   = (const float*)d_in[12];
    const float* att2  = (const float*)d_in[13];
    const float* bias2 = (const float*)d_in[14];
    const float* Wlin  = (const float*)d_in[15];
    const float* blin  = (const float*)d_in[16];
    float* out = (float*)d_out;

    const int* src = ei;
    const int* dst = ei + NE;

    __nv_bfloat16 *xhi, *xlo, *h1hi, *h1lo, *h2hi, *h2lo;
    __nv_bfloat16 *wt1hi, *wt1lo, *wt2hi, *wt2lo, *wtlhi, *wtllo;
    float *xlr1, *xlr2, *cb1, *cb2;
    cudaGetSymbolAddress((void**)&xhi, g_xhi);
    cudaGetSymbolAddress((void**)&xlo, g_xlo);
    cudaGetSymbolAddress((void**)&h1hi, g_h1hi);
    cudaGetSymbolAddress((void**)&h1lo, g_h1lo);
    cudaGetSymbolAddress((void**)&h2hi, g_h2hi);
    cudaGetSymbolAddress((void**)&h2lo, g_h2lo);
    cudaGetSymbolAddress((void**)&wt1hi, g_wt1hi);
    cudaGetSymbolAddress((void**)&wt1lo, g_wt1lo);
    cudaGetSymbolAddress((void**)&wt2hi, g_wt2hi);
    cudaGetSymbolAddress((void**)&wt2lo, g_wt2lo);
    cudaGetSymbolAddress((void**)&wtlhi, g_wtlhi);
    cudaGetSymbolAddress((void**)&wtllo, g_wtllo);
    cudaGetSymbolAddress((void**)&xlr1, g_xlr1);
    cudaGetSymbolAddress((void**)&xlr2, g_xlr2);
    cudaGetSymbolAddress((void**)&cb1, g_cb1);
    cudaGetSymbolAddress((void**)&cb2, g_cb2);

    constexpr int SMEM128 = 2 * (2 * 128 * 40 + 2 * 128 * 40) * 2;  // 81920 B
    constexpr int SMEM64  = 2 * (2 * 128 * 40 + 2 * 64 * 40) * 2;   // 61440 B
    static bool attr_done = false;
    if (!attr_done) {
        cudaFuncSetAttribute(gemm_bf16<128>, cudaFuncAttributeMaxDynamicSharedMemorySize, SMEM128);
        cudaFuncSetAttribute(gemm_bf16<64>,  cudaFuncAttributeMaxDynamicSharedMemorySize, SMEM64);
        attr_done = true;
    }

    // CSR build
    k_zero_deg<<<(NN + 255) / 256, 256>>>();
    k_hist<<<(NE + 255) / 256, 256>>>(dst);
    k_scan<<<1, 1024>>>();
    k_scatter<<<(NE + 255) / 256, 256>>>(src, dst);

    // splits + bias concat
    k_split<<<(NN * 128 + 255) / 256, 256>>>(x, xhi, xlo, NN * 128);
    k_tsplit<<<(128 * 128 + 255) / 256, 256>>>(Wl1, wt1hi, wt1lo, 128, 128);
    k_tsplit<<<(128 * 128 + 255) / 256, 256>>>(Wr1, wt1hi + 128 * 128, wt1lo + 128 * 128, 128, 128);
    k_tsplit<<<(128 * 512 + 255) / 256, 256>>>(Wl2, wt2hi, wt2lo, 128, 512);
    k_tsplit<<<(128 * 512 + 255) / 256, 256>>>(Wr2, wt2hi + 512 * 128, wt2lo + 512 * 128, 128, 512);
    k_tsplit<<<(512 * 64 + 255) / 256, 256>>>(Wlin, wtlhi, wtllo, 512, 64);
    k_bias<<<4, 256>>>(bl1, br1, bl2, br2);

    const int MB = (NN + 127) / 128;  // 157

    // Layer 1: one GEMM (N=256 = [xl|xr]) then fused attention
    gemm_bf16<128><<<dim3(2, MB), 256, SMEM128>>>(xhi, xlo, wt1hi, wt1lo, cb1, xlr1, NN, 256, 128);
    k_agg<128><<<NN / 8, 256>>>(xlr1, 256, 128, att1, bias1, h1hi, h1lo);

    // Layer 2: one GEMM (N=1024 = [xl|xr])
    gemm_bf16<128><<<dim3(8, MB), 256, SMEM128>>>(h1hi, h1lo, wt2hi, wt2lo, cb2, xlr2, NN, 1024, 128);
    k_agg<512><<<NN / 8, 256>>>(xlr2, 1024, 512, att2, bias2, h2hi, h2lo);

    // Output linear (N=64, K=512)
    gemm_bf16<64><<<dim3(1, MB), 256, SMEM64>>>(h2hi, h2lo, wtlhi, wtllo, blin, out, NN, 64, 512);
}

// round 6
// speedup vs baseline: 2.0775x; 1.1054x over previous
#include <cuda_runtime.h>
#include <cuda_bf16.h>
#include <cstdint>

#define NN 20000
#define NE 160000

// ---------------- scratch (device globals: allocation-free) ----------------
__device__ __nv_bfloat16 g_xhi[NN * 128], g_xlo[NN * 128];
__device__ float g_xlr1[NN * 256];
__device__ __nv_bfloat16 g_h1hi[NN * 128], g_h1lo[NN * 128];
__device__ float g_xlr2[NN * 1024];
__device__ __nv_bfloat16 g_h2hi[NN * 512], g_h2lo[NN * 512];
__device__ __nv_bfloat16 g_wt1hi[256 * 128],  g_wt1lo[256 * 128];
__device__ __nv_bfloat16 g_wt2hi[1024 * 128], g_wt2lo[1024 * 128];
__device__ __nv_bfloat16 g_wtlhi[64 * 512],   g_wtllo[64 * 512];
__device__ float g_cb1[256];
__device__ float g_cb2[1024];
__device__ int g_deg[NN];
__device__ int g_rowptr[NN + 1];
__device__ int g_cursor[NN];
__device__ int g_col[NE];

// ---------------- helpers ----------------
__device__ __forceinline__ uint32_t smem_u32(const void* p) {
    uint32_t a;
    asm("{ .reg .u64 t; cvta.to.shared.u64 t, %1; cvt.u32.u64 %0, t; }" : "=r"(a) : "l"(p));
    return a;
}
__device__ __forceinline__ void cp_async16(uint32_t dst, const void* src, bool pred) {
    int sz = pred ? 16 : 0;
    asm volatile("cp.async.cg.shared.global [%0], [%1], 16, %2;"
                 :: "r"(dst), "l"(src), "r"(sz) : "memory");
}
__device__ __forceinline__ void cp_commit() {
    asm volatile("cp.async.commit_group;" ::: "memory");
}
template <int W> __device__ __forceinline__ void cp_wait() {
    asm volatile("cp.async.wait_group %0;" :: "n"(W) : "memory");
}
__device__ __forceinline__ void split1(float a, __nv_bfloat16& h, __nv_bfloat16& l) {
    h = __float2bfloat16(a);
    l = __float2bfloat16(a - __bfloat162float(h));
}
__device__ __forceinline__ void mma_bf16(float* c, const uint32_t* a, const uint32_t* b) {
    asm volatile("mma.sync.aligned.m16n8k16.row.col.f32.bf16.bf16.f32 "
                 "{%0,%1,%2,%3}, {%4,%5,%6,%7}, {%8,%9}, {%0,%1,%2,%3};"
                 : "+f"(c[0]), "+f"(c[1]), "+f"(c[2]), "+f"(c[3])
                 : "r"(a[0]), "r"(a[1]), "r"(a[2]), "r"(a[3]), "r"(b[0]), "r"(b[1]));
}
__device__ __forceinline__ void ldsm_x4(uint32_t* r, uint32_t addr) {
    asm volatile("ldmatrix.sync.aligned.m8n8.x4.shared.b16 {%0,%1,%2,%3}, [%4];"
                 : "=r"(r[0]), "=r"(r[1]), "=r"(r[2]), "=r"(r[3]) : "r"(addr));
}

// ---------------- fused prep: zero_deg + x split + W transposes + bias -----
__global__ void k_prep(const float* __restrict__ x,
                       const float* __restrict__ Wl1, const float* __restrict__ Wr1,
                       const float* __restrict__ Wl2, const float* __restrict__ Wr2,
                       const float* __restrict__ Wlin,
                       const float* __restrict__ bl1, const float* __restrict__ br1,
                       const float* __restrict__ bl2, const float* __restrict__ br2) {
    const int S0 = NN;
    const int S1 = S0 + NN * 128;
    const int S2 = S1 + 16384;
    const int S3 = S2 + 16384;
    const int S4 = S3 + 65536;
    const int S5 = S4 + 65536;
    const int S6 = S5 + 32768;
    const int S7 = S6 + 1280;
    int i = blockIdx.x * blockDim.x + threadIdx.x;
    if (i < S0) {
        g_deg[i] = 0;
    } else if (i < S1) {
        int j = i - S0;
        __nv_bfloat16 h, l;
        split1(x[j], h, l);
        g_xhi[j] = h; g_xlo[j] = l;
    } else if (i < S2) {
        int j = i - S1, k = j >> 7, n = j & 127;          // K=128, N=128
        __nv_bfloat16 h, l;
        split1(Wl1[j], h, l);
        g_wt1hi[n * 128 + k] = h; g_wt1lo[n * 128 + k] = l;
    } else if (i < S3) {
        int j = i - S2, k = j >> 7, n = j & 127;
        __nv_bfloat16 h, l;
        split1(Wr1[j], h, l);
        g_wt1hi[128 * 128 + n * 128 + k] = h; g_wt1lo[128 * 128 + n * 128 + k] = l;
    } else if (i < S4) {
        int j = i - S3, k = j >> 9, n = j & 511;          // K=128, N=512
        __nv_bfloat16 h, l;
        split1(Wl2[j], h, l);
        g_wt2hi[n * 128 + k] = h; g_wt2lo[n * 128 + k] = l;
    } else if (i < S5) {
        int j = i - S4, k = j >> 9, n = j & 511;
        __nv_bfloat16 h, l;
        split1(Wr2[j], h, l);
        g_wt2hi[512 * 128 + n * 128 + k] = h; g_wt2lo[512 * 128 + n * 128 + k] = l;
    } else if (i < S6) {
        int j = i - S5, k = j >> 6, n = j & 63;           // K=512, N=64
        __nv_bfloat16 h, l;
        split1(Wlin[j], h, l);
        g_wtlhi[n * 512 + k] = h; g_wtllo[n * 512 + k] = l;
    } else if (i < S7) {
        int j = i - S6;
        if (j < 256) g_cb1[j] = (j < 128) ? bl1[j] : br1[j - 128];
        else {
            int b = j - 256;
            g_cb2[b] = (b < 512) ? bl2[b] : br2[b - 512];
        }
    }
}
#define PREP_TOTAL (NN + NN * 128 + 16384 * 2 + 65536 * 2 + 32768 + 1280)

// ---------------- CSR build (counting sort by dst) ----------------
__global__ void k_hist(const int* __restrict__ dst) {
    int e = blockIdx.x * blockDim.x + threadIdx.x;
    if (e < NE) atomicAdd(&g_deg[dst[e]], 1);
}
__global__ void k_scan() {
    __shared__ int s[1024];
    const int CH = (NN + 1023) / 1024;
    int t = threadIdx.x;
    int start = t * CH;
    int end = start + CH < NN ? start + CH : NN;
    int sum = 0;
    for (int i = start; i < end; i++) sum += g_deg[i];
    s[t] = sum;
    __syncthreads();
    for (int off = 1; off < 1024; off <<= 1) {
        int v = (t >= off) ? s[t - off] : 0;
        __syncthreads();
        s[t] += v;
        __syncthreads();
    }
    int run = (t == 0) ? 0 : s[t - 1];
    for (int i = start; i < end; i++) {
        g_rowptr[i] = run;
        g_cursor[i] = run;
        run += g_deg[i];
    }
    if (t == 1023) g_rowptr[NN] = s[1023];
}
__global__ void k_scatter(const int* __restrict__ src, const int* __restrict__ dst) {
    int e = blockIdx.x * blockDim.x + threadIdx.x;
    if (e < NE) {
        int d = dst[e];
        int pos = atomicAdd(&g_cursor[d], 1);
        g_col[pos] = src[e];
    }
}

// ---------------- pipelined bf16-split GEMM (ldmatrix + mma.sync) ---------
template <int BN>
__global__ void __launch_bounds__(256)
gemm_bf16(const __nv_bfloat16* __restrict__ Ahi, const __nv_bfloat16* __restrict__ Alo,
          const __nv_bfloat16* __restrict__ Bhi, const __nv_bfloat16* __restrict__ Blo,
          const float* __restrict__ bias, float* __restrict__ C,
          int M, int N, int K) {
    constexpr int BK = 32;
    constexpr int STR = 40;
    constexpr int ASZ = 128 * STR;
    constexpr int BSZ = BN * STR;
    constexpr int STAGE = 2 * ASZ + 2 * BSZ;
    constexpr int NT = BN / 32;
    extern __shared__ __nv_bfloat16 sm[];

    const int tid = threadIdx.x;
    const int wid = tid >> 5;
    const int lane = tid & 31;
    const int wm = wid & 1;
    const int wn = wid >> 1;
    const int gid = lane >> 2;
    const int tig = lane & 3;
    const int m0 = blockIdx.y * 128;
    const int n0 = blockIdx.x * BN;
    const int nk = K / BK;

    const int a_row = wm * 64 + (lane & 7) + ((lane >> 3) & 1) * 8;
    const int a_koff = (lane & 16) >> 1;
    const int b_row = wn * (NT * 8) + (lane & 7) + ((lane & 16) >> 1);
    const int b_koff = lane & 8;

    float c[4][NT][4];
#pragma unroll
    for (int mt = 0; mt < 4; mt++)
#pragma unroll
        for (int nt = 0; nt < NT; nt++)
#pragma unroll
            for (int r = 0; r < 4; r++) c[mt][nt][r] = 0.f;

    auto load_stage = [&](int kc, int s) {
        const int k0 = kc * BK;
        __nv_bfloat16* base = sm + s * STAGE;
#pragma unroll
        for (int j = 0; j < 2; j++) {
            int i = tid + j * 256;
            int row = i >> 2, ch = i & 3;
            int gm = m0 + row;
            bool p = gm < M;
            int gmc = p ? gm : (M - 1);
            size_t goff = (size_t)gmc * K + k0 + ch * 8;
            uint32_t d = smem_u32(base + row * STR + ch * 8);
            cp_async16(d, Ahi + goff, p);
            cp_async16(d + ASZ * 2, Alo + goff, p);
        }
#pragma unroll
        for (int j = 0; j < BN / 64; j++) {
            int i = tid + j * 256;
            int row = i >> 2, ch = i & 3;
            size_t goff = (size_t)(n0 + row) * K + k0 + ch * 8;
            uint32_t d = smem_u32(base + 2 * ASZ + row * STR + ch * 8);
            cp_async16(d, Bhi + goff, true);
            cp_async16(d + BSZ * 2, Blo + goff, true);
        }
    };

    load_stage(0, 0);
    cp_commit();

    for (int kc = 0; kc < nk; kc++) {
        const int s = kc & 1;
        if (kc + 1 < nk) {
            load_stage(kc + 1, s ^ 1);
            cp_commit();
            cp_wait<1>();
        } else {
            cp_wait<0>();
        }
        __syncthreads();

        const uint32_t stg = smem_u32(sm + s * STAGE);
        const uint32_t ah_base = stg + (a_row * STR + a_koff) * 2;
        const uint32_t al_base = ah_base + ASZ * 2;
        const uint32_t bh_base = stg + 2 * ASZ * 2 + (b_row * STR + b_koff) * 2;
        const uint32_t bl_base = bh_base + BSZ * 2;

#pragma unroll
        for (int kb = 0; kb < BK; kb += 16) {
            uint32_t bfh[NT][2], bfl[NT][2];
#pragma unroll
            for (int p = 0; p < NT / 2; p++) {
                uint32_t off = (p * 16 * STR + kb) * 2;
                ldsm_x4(&bfh[2 * p][0], bh_base + off);
                ldsm_x4(&bfl[2 * p][0], bl_base + off);
            }
#pragma unroll
            for (int mt = 0; mt < 4; mt++) {
                uint32_t afh[4], afl[4];
                uint32_t off = (mt * 16 * STR + kb) * 2;
                ldsm_x4(afh, ah_base + off);
                ldsm_x4(afl, al_base + off);
#pragma unroll
                for (int nt = 0; nt < NT; nt++) {
                    mma_bf16(c[mt][nt], afh, bfh[nt]);
                    mma_bf16(c[mt][nt], afh, bfl[nt]);
                    mma_bf16(c[mt][nt], afl, bfh[nt]);
                }
            }
        }
        __syncthreads();
    }

#pragma unroll
    for (int mt = 0; mt < 4; mt++) {
        int r0 = m0 + wm * 64 + mt * 16 + gid;
#pragma unroll
        for (int nt = 0; nt < NT; nt++) {
            int col = n0 + wn * (NT * 8) + nt * 8 + tig * 2;
            float b0 = bias[col], b1 = bias[col + 1];
            if (r0 < M) {
                float2 v0 = make_float2(c[mt][nt][0] + b0, c[mt][nt][1] + b1);
                *reinterpret_cast<float2*>(C + (size_t)r0 * N + col) = v0;
            }
            if (r0 + 8 < M) {
                float2 v1 = make_float2(c[mt][nt][2] + b0, c[mt][nt][3] + b1);
                *reinterpret_cast<float2*>(C + (size_t)(r0 + 8) * N + col) = v1;
            }
        }
    }
}

// ---------------- fused GATv2 edge-softmax + aggregation (prefetched) ------
template <int D>
__global__ void __launch_bounds__(256, 2)
k_agg(const float* __restrict__ xlr, int SR, int XO,
      const float* __restrict__ att, const float* __restrict__ bias,
      __nv_bfloat16* __restrict__ ohi, __nv_bfloat16* __restrict__ olo) {
    constexpr int CPL = D / 32;
    constexpr int V = CPL / 4;

    int warp = (blockIdx.x * blockDim.x + threadIdx.x) >> 5;
    int lane = threadIdx.x & 31;
    if (warp >= NN) return;
    const int node = warp;
    const int base = lane * CPL;

    float attv[CPL], xrv[CPL];
#pragma unroll
    for (int j = 0; j < V; j++) {
        float4 a4 = *reinterpret_cast<const float4*>(att + base + 4 * j);
        float4 r4 = *reinterpret_cast<const float4*>(xlr + (size_t)node * SR + XO + base + 4 * j);
        attv[4 * j + 0] = a4.x; attv[4 * j + 1] = a4.y;
        attv[4 * j + 2] = a4.z; attv[4 * j + 3] = a4.w;
        xrv[4 * j + 0] = r4.x; xrv[4 * j + 1] = r4.y;
        xrv[4 * j + 2] = r4.z; xrv[4 * j + 3] = r4.w;
    }

    float m = -3.402823466e38f;
    float ssum = 0.f;
    float acc[CPL];
#pragma unroll
    for (int c = 0; c < CPL; c++) acc[c] = 0.f;

    const int rs = g_rowptr[node];
    const int re = g_rowptr[node + 1];

    if (rs < re) {
        // prefetch first edge
        int s = g_col[rs];
        float xlv[CPL];
#pragma unroll
        for (int j = 0; j < V; j++) {
            float4 v = *reinterpret_cast<const float4*>(xlr + (size_t)s * SR + base + 4 * j);
            xlv[4 * j + 0] = v.x; xlv[4 * j + 1] = v.y;
            xlv[4 * j + 2] = v.z; xlv[4 * j + 3] = v.w;
        }
        for (int p = rs; p < re; p++) {
            // issue next edge's gather before using current
            int sn = (p + 1 < re) ? g_col[p + 1] : s;
            float xln[CPL];
#pragma unroll
            for (int j = 0; j < V; j++) {
                float4 v = *reinterpret_cast<const float4*>(xlr + (size_t)sn * SR + base + 4 * j);
                xln[4 * j + 0] = v.x; xln[4 * j + 1] = v.y;
                xln[4 * j + 2] = v.z; xln[4 * j + 3] = v.w;
            }
            float partial = 0.f;
#pragma unroll
            for (int c = 0; c < CPL; c++) {
                float e = xlv[c] + xrv[c];
                e = (e >= 0.f) ? e : 0.2f * e;
                partial = fmaf(attv[c], e, partial);
            }
            partial += __shfl_xor_sync(0xffffffffu, partial, 1);
            partial += __shfl_xor_sync(0xffffffffu, partial, 2);
            partial += __shfl_xor_sync(0xffffffffu, partial, 4);

            float mnew = fmaxf(m, partial);
            float fac = __expf(m - mnew);
            float w = __expf(partial - mnew);
            ssum = ssum * fac + w;
#pragma unroll
            for (int c = 0; c < CPL; c++) acc[c] = fmaf(acc[c], fac, w * xlv[c]);
            m = mnew;
#pragma unroll
            for (int c = 0; c < CPL; c++) xlv[c] = xln[c];
        }
    }

    float inv = (ssum > 0.f) ? (1.f / ssum) : 0.f;
#pragma unroll
    for (int j = 0; j < CPL / 2; j++) {
        float v0 = fmaxf(fmaf(acc[2 * j], inv, bias[base + 2 * j]), 0.f);
        float v1 = fmaxf(fmaf(acc[2 * j + 1], inv, bias[base + 2 * j + 1]), 0.f);
        __nv_bfloat16 h0, l0, h1, l1;
        split1(v0, h0, l0);
        split1(v1, h1, l1);
        __nv_bfloat162 hp = __halves2bfloat162(h0, h1);
        __nv_bfloat162 lp = __halves2bfloat162(l0, l1);
        *reinterpret_cast<__nv_bfloat162*>(ohi + (size_t)node * D + base + 2 * j) = hp;
        *reinterpret_cast<__nv_bfloat162*>(olo + (size_t)node * D + base + 2 * j) = lp;
    }
}

// ---------------- launch ----------------
extern "C" void kernel_launch(void* const* d_in, const int* in_sizes, int n_in,
                              void* d_out, int out_size) {
    (void)in_sizes; (void)n_in; (void)out_size;
    const float* x     = (const float*)d_in[0];
    const int*   ei    = (const int*)  d_in[1];
    const float* Wl1   = (const float*)d_in[3];
    const float* bl1   = (const float*)d_in[4];
    const float* Wr1   = (const float*)d_in[5];
    const float* br1   = (const float*)d_in[6];
    const float* att1  = (const float*)d_in[7];
    const float* bias1 = (const float*)d_in[8];
    const float* Wl2   = (const float*)d_in[9];
    const float* bl2   = (const float*)d_in[10];
    const float* Wr2   = (const float*)d_in[11];
    const float* br2   = (const float*)d_in[12];
    const float* att2  = (const float*)d_in[13];
    const float* bias2 = (const float*)d_in[14];
    const float* Wlin  = (const float*)d_in[15];
    const float* blin  = (const float*)d_in[16];
    float* out = (float*)d_out;

    const int* src = ei;
    const int* dst = ei + NE;

    __nv_bfloat16 *xhi, *xlo, *h1hi, *h1lo, *h2hi, *h2lo;
    __nv_bfloat16 *wt1hi, *wt1lo, *wt2hi, *wt2lo, *wtlhi, *wtllo;
    float *xlr1, *xlr2, *cb1, *cb2;
    cudaGetSymbolAddress((void**)&xhi, g_xhi);
    cudaGetSymbolAddress((void**)&xlo, g_xlo);
    cudaGetSymbolAddress((void**)&h1hi, g_h1hi);
    cudaGetSymbolAddress((void**)&h1lo, g_h1lo);
    cudaGetSymbolAddress((void**)&h2hi, g_h2hi);
    cudaGetSymbolAddress((void**)&h2lo, g_h2lo);
    cudaGetSymbolAddress((void**)&wt1hi, g_wt1hi);
    cudaGetSymbolAddress((void**)&wt1lo, g_wt1lo);
    cudaGetSymbolAddress((void**)&wt2hi, g_wt2hi);
    cudaGetSymbolAddress((void**)&wt2lo, g_wt2lo);
    cudaGetSymbolAddress((void**)&wtlhi, g_wtlhi);
    cudaGetSymbolAddress((void**)&wtllo, g_wtllo);
    cudaGetSymbolAddress((void**)&xlr1, g_xlr1);
    cudaGetSymbolAddress((void**)&xlr2, g_xlr2);
    cudaGetSymbolAddress((void**)&cb1, g_cb1);
    cudaGetSymbolAddress((void**)&cb2, g_cb2);

    constexpr int SMEM128 = 2 * (2 * 128 * 40 + 2 * 128 * 40) * 2;
    constexpr int SMEM64  = 2 * (2 * 128 * 40 + 2 * 64 * 40) * 2;
    static cudaStream_t s_aux = nullptr;
    static cudaEvent_t e_fork = nullptr, e_csr = nullptr;
    if (!s_aux) {
        cudaFuncSetAttribute(gemm_bf16<128>, cudaFuncAttributeMaxDynamicSharedMemorySize, SMEM128);
        cudaFuncSetAttribute(gemm_bf16<64>,  cudaFuncAttributeMaxDynamicSharedMemorySize, SMEM64);
        cudaStreamCreateWithFlags(&s_aux, cudaStreamNonBlocking);
        cudaEventCreateWithFlags(&e_fork, cudaEventDisableTiming);
        cudaEventCreateWithFlags(&e_csr, cudaEventDisableTiming);
    }

    const int MB = (NN + 127) / 128;  // 157

    // #1: fused prep (zeroes deg, splits x + weights, concats biases)
    k_prep<<<(PREP_TOTAL + 255) / 256, 256>>>(x, Wl1, Wr1, Wl2, Wr2, Wlin, bl1, br1, bl2, br2);

    // fork CSR build onto side stream (independent of GEMM1 chain)
    cudaEventRecord(e_fork, 0);
    cudaStreamWaitEvent(s_aux, e_fork, 0);
    k_hist<<<(NE + 255) / 256, 256, 0, s_aux>>>(dst);                 // #2
    k_scan<<<1, 1024, 0, s_aux>>>();                                  // #3

    // #4 (profiled slot): layer-1 GEMM, N=256 = [xl|xr]
    gemm_bf16<128><<<dim3(2, MB), 256, SMEM128>>>(xhi, xlo, wt1hi, wt1lo, cb1, xlr1, NN, 256, 128);

    k_scatter<<<(NE + 255) / 256, 256, 0, s_aux>>>(src, dst);         // #5
    cudaEventRecord(e_csr, s_aux);
    cudaStreamWaitEvent(0, e_csr, 0);

    // layer-1 attention, then layer-2 GEMM + attention, then output linear
    k_agg<128><<<NN / 8, 256>>>(xlr1, 256, 128, att1, bias1, h1hi, h1lo);
    gemm_bf16<128><<<dim3(8, MB), 256, SMEM128>>>(h1hi, h1lo, wt2hi, wt2lo, cb2, xlr2, NN, 1024, 128);
    k_agg<512><<<NN / 8, 256>>>(xlr2, 1024, 512, att2, bias2, h2hi, h2lo);
    gemm_bf16<64><<<dim3(1, MB), 256, SMEM64>>>(h2hi, h2lo, wtlhi, wtllo, blin, out, NN, 64, 512);
}

// round 7
// speedup vs baseline: 2.1781x; 1.0484x over previous
#include <cuda_runtime.h>
#include <cuda_bf16.h>
#include <cstdint>

#define NN 20000
#define NE 160000

// ---------------- scratch (device globals: allocation-free) ----------------
__device__ __nv_bfloat16 g_xhi[NN * 128], g_xlo[NN * 128];
__device__ float g_xlr1[NN * 256];
__device__ __nv_bfloat16 g_h1hi[NN * 128], g_h1lo[NN * 128];
__device__ float g_xlr2[NN * 1024];
__device__ __nv_bfloat16 g_h2hi[NN * 512], g_h2lo[NN * 512];
__device__ __nv_bfloat16 g_wt1hi[256 * 128],  g_wt1lo[256 * 128];
__device__ __nv_bfloat16 g_wt2hi[1024 * 128], g_wt2lo[1024 * 128];
__device__ __nv_bfloat16 g_wtlhi[64 * 512],   g_wtllo[64 * 512];
__device__ float g_cb1[256];
__device__ float g_cb2[1024];
__device__ int g_deg[NN];
__device__ int g_rowptr[NN + 1];
__device__ int g_cursor[NN];
__device__ int g_col[NE];

// ---------------- helpers ----------------
__device__ __forceinline__ uint32_t smem_u32(const void* p) {
    uint32_t a;
    asm("{ .reg .u64 t; cvta.to.shared.u64 t, %1; cvt.u32.u64 %0, t; }" : "=r"(a) : "l"(p));
    return a;
}
__device__ __forceinline__ void cp_async16(uint32_t dst, const void* src, bool pred) {
    int sz = pred ? 16 : 0;
    asm volatile("cp.async.cg.shared.global [%0], [%1], 16, %2;"
                 :: "r"(dst), "l"(src), "r"(sz) : "memory");
}
__device__ __forceinline__ void cp_commit() {
    asm volatile("cp.async.commit_group;" ::: "memory");
}
template <int W> __device__ __forceinline__ void cp_wait() {
    asm volatile("cp.async.wait_group %0;" :: "n"(W) : "memory");
}
__device__ __forceinline__ void split1(float a, __nv_bfloat16& h, __nv_bfloat16& l) {
    h = __float2bfloat16(a);
    l = __float2bfloat16(a - __bfloat162float(h));
}
__device__ __forceinline__ void mma_bf16(float* c, const uint32_t* a, const uint32_t* b) {
    asm volatile("mma.sync.aligned.m16n8k16.row.col.f32.bf16.bf16.f32 "
                 "{%0,%1,%2,%3}, {%4,%5,%6,%7}, {%8,%9}, {%0,%1,%2,%3};"
                 : "+f"(c[0]), "+f"(c[1]), "+f"(c[2]), "+f"(c[3])
                 : "r"(a[0]), "r"(a[1]), "r"(a[2]), "r"(a[3]), "r"(b[0]), "r"(b[1]));
}
__device__ __forceinline__ void ldsm_x4(uint32_t* r, uint32_t addr) {
    asm volatile("ldmatrix.sync.aligned.m8n8.x4.shared.b16 {%0,%1,%2,%3}, [%4];"
                 : "=r"(r[0]), "=r"(r[1]), "=r"(r[2]), "=r"(r[3]) : "r"(addr));
}

// ---------------- fused prep: zero_deg + x split + W transposes + bias -----
__global__ void k_prep(const float* __restrict__ x,
                       const float* __restrict__ Wl1, const float* __restrict__ Wr1,
                       const float* __restrict__ Wl2, const float* __restrict__ Wr2,
                       const float* __restrict__ Wlin,
                       const float* __restrict__ bl1, const float* __restrict__ br1,
                       const float* __restrict__ bl2, const float* __restrict__ br2) {
    const int S0 = NN;
    const int S1 = S0 + NN * 128;
    const int S2 = S1 + 16384;
    const int S3 = S2 + 16384;
    const int S4 = S3 + 65536;
    const int S5 = S4 + 65536;
    const int S6 = S5 + 32768;
    const int S7 = S6 + 1280;
    int i = blockIdx.x * blockDim.x + threadIdx.x;
    if (i < S0) {
        g_deg[i] = 0;
    } else if (i < S1) {
        int j = i - S0;
        __nv_bfloat16 h, l;
        split1(x[j], h, l);
        g_xhi[j] = h; g_xlo[j] = l;
    } else if (i < S2) {
        int j = i - S1, k = j >> 7, n = j & 127;
        __nv_bfloat16 h, l;
        split1(Wl1[j], h, l);
        g_wt1hi[n * 128 + k] = h; g_wt1lo[n * 128 + k] = l;
    } else if (i < S3) {
        int j = i - S2, k = j >> 7, n = j & 127;
        __nv_bfloat16 h, l;
        split1(Wr1[j], h, l);
        g_wt1hi[128 * 128 + n * 128 + k] = h; g_wt1lo[128 * 128 + n * 128 + k] = l;
    } else if (i < S4) {
        int j = i - S3, k = j >> 9, n = j & 511;
        __nv_bfloat16 h, l;
        split1(Wl2[j], h, l);
        g_wt2hi[n * 128 + k] = h; g_wt2lo[n * 128 + k] = l;
    } else if (i < S5) {
        int j = i - S4, k = j >> 9, n = j & 511;
        __nv_bfloat16 h, l;
        split1(Wr2[j], h, l);
        g_wt2hi[512 * 128 + n * 128 + k] = h; g_wt2lo[512 * 128 + n * 128 + k] = l;
    } else if (i < S6) {
        int j = i - S5, k = j >> 6, n = j & 63;
        __nv_bfloat16 h, l;
        split1(Wlin[j], h, l);
        g_wtlhi[n * 512 + k] = h; g_wtllo[n * 512 + k] = l;
    } else if (i < S7) {
        int j = i - S6;
        if (j < 256) g_cb1[j] = (j < 128) ? bl1[j] : br1[j - 128];
        else {
            int b = j - 256;
            g_cb2[b] = (b < 512) ? bl2[b] : br2[b - 512];
        }
    }
}
#define PREP_TOTAL (NN + NN * 128 + 16384 * 2 + 65536 * 2 + 32768 + 1280)

// ---------------- CSR build (counting sort by dst) ----------------
__global__ void k_hist(const int* __restrict__ dst) {
    int e = blockIdx.x * blockDim.x + threadIdx.x;
    if (e < NE) atomicAdd(&g_deg[dst[e]], 1);
}
__global__ void k_scan() {
    __shared__ int s[1024];
    const int CH = (NN + 1023) / 1024;
    int t = threadIdx.x;
    int start = t * CH;
    int end = start + CH < NN ? start + CH : NN;
    int sum = 0;
    for (int i = start; i < end; i++) sum += g_deg[i];
    s[t] = sum;
    __syncthreads();
    for (int off = 1; off < 1024; off <<= 1) {
        int v = (t >= off) ? s[t - off] : 0;
        __syncthreads();
        s[t] += v;
        __syncthreads();
    }
    int run = (t == 0) ? 0 : s[t - 1];
    for (int i = start; i < end; i++) {
        g_rowptr[i] = run;
        g_cursor[i] = run;
        run += g_deg[i];
    }
    if (t == 1023) g_rowptr[NN] = s[1023];
}
__global__ void k_scatter(const int* __restrict__ src, const int* __restrict__ dst) {
    int e = blockIdx.x * blockDim.x + threadIdx.x;
    if (e < NE) {
        int d = dst[e];
        int pos = atomicAdd(&g_cursor[d], 1);
        g_col[pos] = src[e];
    }
}

// ---------------- pipelined bf16-split GEMM (ldmatrix + mma.sync) ---------
// __launch_bounds__(256, 2): cap regs at 128 so 2 CTAs/SM are resident.
template <int BN>
__global__ void __launch_bounds__(256, 2)
gemm_bf16(const __nv_bfloat16* __restrict__ Ahi, const __nv_bfloat16* __restrict__ Alo,
          const __nv_bfloat16* __restrict__ Bhi, const __nv_bfloat16* __restrict__ Blo,
          const float* __restrict__ bias, float* __restrict__ C,
          int M, int N, int K) {
    constexpr int BK = 32;
    constexpr int STR = 40;
    constexpr int ASZ = 128 * STR;
    constexpr int BSZ = BN * STR;
    constexpr int STAGE = 2 * ASZ + 2 * BSZ;
    constexpr int NT = BN / 32;
    extern __shared__ __nv_bfloat16 sm[];

    const int tid = threadIdx.x;
    const int wid = tid >> 5;
    const int lane = tid & 31;
    const int wm = wid & 1;
    const int wn = wid >> 1;
    const int gid = lane >> 2;
    const int tig = lane & 3;
    const int m0 = blockIdx.y * 128;
    const int n0 = blockIdx.x * BN;
    const int nk = K / BK;

    const int a_row = wm * 64 + (lane & 7) + ((lane >> 3) & 1) * 8;
    const int a_koff = (lane & 16) >> 1;
    const int b_row = wn * (NT * 8) + (lane & 7) + ((lane & 16) >> 1);
    const int b_koff = lane & 8;

    float c[4][NT][4];
#pragma unroll
    for (int mt = 0; mt < 4; mt++)
#pragma unroll
        for (int nt = 0; nt < NT; nt++)
#pragma unroll
            for (int r = 0; r < 4; r++) c[mt][nt][r] = 0.f;

    auto load_stage = [&](int kc, int s) {
        const int k0 = kc * BK;
        __nv_bfloat16* base = sm + s * STAGE;
#pragma unroll
        for (int j = 0; j < 2; j++) {
            int i = tid + j * 256;
            int row = i >> 2, ch = i & 3;
            int gm = m0 + row;
            bool p = gm < M;
            int gmc = p ? gm : (M - 1);
            size_t goff = (size_t)gmc * K + k0 + ch * 8;
            uint32_t d = smem_u32(base + row * STR + ch * 8);
            cp_async16(d, Ahi + goff, p);
            cp_async16(d + ASZ * 2, Alo + goff, p);
        }
#pragma unroll
        for (int j = 0; j < BN / 64; j++) {
            int i = tid + j * 256;
            int row = i >> 2, ch = i & 3;
            size_t goff = (size_t)(n0 + row) * K + k0 + ch * 8;
            uint32_t d = smem_u32(base + 2 * ASZ + row * STR + ch * 8);
            cp_async16(d, Bhi + goff, true);
            cp_async16(d + BSZ * 2, Blo + goff, true);
        }
    };

    load_stage(0, 0);
    cp_commit();

    for (int kc = 0; kc < nk; kc++) {
        const int s = kc & 1;
        if (kc + 1 < nk) {
            load_stage(kc + 1, s ^ 1);
            cp_commit();
            cp_wait<1>();
        } else {
            cp_wait<0>();
        }
        __syncthreads();

        const uint32_t stg = smem_u32(sm + s * STAGE);
        const uint32_t ah_base = stg + (a_row * STR + a_koff) * 2;
        const uint32_t al_base = ah_base + ASZ * 2;
        const uint32_t bh_base = stg + 2 * ASZ * 2 + (b_row * STR + b_koff) * 2;
        const uint32_t bl_base = bh_base + BSZ * 2;

#pragma unroll
        for (int kb = 0; kb < BK; kb += 16) {
            uint32_t bfh[NT][2], bfl[NT][2];
#pragma unroll
            for (int p = 0; p < NT / 2; p++) {
                uint32_t off = (p * 16 * STR + kb) * 2;
                ldsm_x4(&bfh[2 * p][0], bh_base + off);
                ldsm_x4(&bfl[2 * p][0], bl_base + off);
            }
#pragma unroll
            for (int mt = 0; mt < 4; mt++) {
                uint32_t afh[4], afl[4];
                uint32_t off = (mt * 16 * STR + kb) * 2;
                ldsm_x4(afh, ah_base + off);
                ldsm_x4(afl, al_base + off);
#pragma unroll
                for (int nt = 0; nt < NT; nt++) {
                    mma_bf16(c[mt][nt], afh, bfh[nt]);
                    mma_bf16(c[mt][nt], afh, bfl[nt]);
                    mma_bf16(c[mt][nt], afl, bfh[nt]);
                }
            }
        }
        __syncthreads();
    }

#pragma unroll
    for (int mt = 0; mt < 4; mt++) {
        int r0 = m0 + wm * 64 + mt * 16 + gid;
#pragma unroll
        for (int nt = 0; nt < NT; nt++) {
            int col = n0 + wn * (NT * 8) + nt * 8 + tig * 2;
            float b0 = bias[col], b1 = bias[col + 1];
            if (r0 < M) {
                float2 v0 = make_float2(c[mt][nt][0] + b0, c[mt][nt][1] + b1);
                *reinterpret_cast<float2*>(C + (size_t)r0 * N + col) = v0;
            }
            if (r0 + 8 < M) {
                float2 v1 = make_float2(c[mt][nt][2] + b0, c[mt][nt][3] + b1);
                *reinterpret_cast<float2*>(C + (size_t)(r0 + 8) * N + col) = v1;
            }
        }
    }
}

// ---------------- fused GATv2 edge-softmax + aggregation (prefetched) ------
template <int D>
__global__ void __launch_bounds__(256, 2)
k_agg(const float* __restrict__ xlr, int SR, int XO,
      const float* __restrict__ att, const float* __restrict__ bias,
      __nv_bfloat16* __restrict__ ohi, __nv_bfloat16* __restrict__ olo) {
    constexpr int CPL = D / 32;
    constexpr int V = CPL / 4;

    int warp = (blockIdx.x * blockDim.x + threadIdx.x) >> 5;
    int lane = threadIdx.x & 31;
    if (warp >= NN) return;
    const int node = warp;
    const int base = lane * CPL;

    float attv[CPL], xrv[CPL];
#pragma unroll
    for (int j = 0; j < V; j++) {
        float4 a4 = *reinterpret_cast<const float4*>(att + base + 4 * j);
        float4 r4 = *reinterpret_cast<const float4*>(xlr + (size_t)node * SR + XO + base + 4 * j);
        attv[4 * j + 0] = a4.x; attv[4 * j + 1] = a4.y;
        attv[4 * j + 2] = a4.z; attv[4 * j + 3] = a4.w;
        xrv[4 * j + 0] = r4.x; xrv[4 * j + 1] = r4.y;
        xrv[4 * j + 2] = r4.z; xrv[4 * j + 3] = r4.w;
    }

    float m = -3.402823466e38f;
    float ssum = 0.f;
    float acc[CPL];
#pragma unroll
    for (int c = 0; c < CPL; c++) acc[c] = 0.f;

    const int rs = g_rowptr[node];
    const int re = g_rowptr[node + 1];

    if (rs < re) {
        int s = g_col[rs];
        float xlv[CPL];
#pragma unroll
        for (int j = 0; j < V; j++) {
            float4 v = *reinterpret_cast<const float4*>(xlr + (size_t)s * SR + base + 4 * j);
            xlv[4 * j + 0] = v.x; xlv[4 * j + 1] = v.y;
            xlv[4 * j + 2] = v.z; xlv[4 * j + 3] = v.w;
        }
        for (int p = rs; p < re; p++) {
            int sn = (p + 1 < re) ? g_col[p + 1] : s;
            float xln[CPL];
#pragma unroll
            for (int j = 0; j < V; j++) {
                float4 v = *reinterpret_cast<const float4*>(xlr + (size_t)sn * SR + base + 4 * j);
                xln[4 * j + 0] = v.x; xln[4 * j + 1] = v.y;
                xln[4 * j + 2] = v.z; xln[4 * j + 3] = v.w;
            }
            float partial = 0.f;
#pragma unroll
            for (int c = 0; c < CPL; c++) {
                float e = xlv[c] + xrv[c];
                e = (e >= 0.f) ? e : 0.2f * e;
                partial = fmaf(attv[c], e, partial);
            }
            partial += __shfl_xor_sync(0xffffffffu, partial, 1);
            partial += __shfl_xor_sync(0xffffffffu, partial, 2);
            partial += __shfl_xor_sync(0xffffffffu, partial, 4);

            float mnew = fmaxf(m, partial);
            float fac = __expf(m - mnew);
            float w = __expf(partial - mnew);
            ssum = ssum * fac + w;
#pragma unroll
            for (int c = 0; c < CPL; c++) acc[c] = fmaf(acc[c], fac, w * xlv[c]);
            m = mnew;
#pragma unroll
            for (int c = 0; c < CPL; c++) xlv[c] = xln[c];
        }
    }

    float inv = (ssum > 0.f) ? (1.f / ssum) : 0.f;
#pragma unroll
    for (int j = 0; j < CPL / 2; j++) {
        float v0 = fmaxf(fmaf(acc[2 * j], inv, bias[base + 2 * j]), 0.f);
        float v1 = fmaxf(fmaf(acc[2 * j + 1], inv, bias[base + 2 * j + 1]), 0.f);
        __nv_bfloat16 h0, l0, h1, l1;
        split1(v0, h0, l0);
        split1(v1, h1, l1);
        __nv_bfloat162 hp = __halves2bfloat162(h0, h1);
        __nv_bfloat162 lp = __halves2bfloat162(l0, l1);
        *reinterpret_cast<__nv_bfloat162*>(ohi + (size_t)node * D + base + 2 * j) = hp;
        *reinterpret_cast<__nv_bfloat162*>(olo + (size_t)node * D + base + 2 * j) = lp;
    }
}

// ---------------- launch ----------------
extern "C" void kernel_launch(void* const* d_in, const int* in_sizes, int n_in,
                              void* d_out, int out_size) {
    (void)in_sizes; (void)n_in; (void)out_size;
    const float* x     = (const float*)d_in[0];
    const int*   ei    = (const int*)  d_in[1];
    const float* Wl1   = (const float*)d_in[3];
    const float* bl1   = (const float*)d_in[4];
    const float* Wr1   = (const float*)d_in[5];
    const float* br1   = (const float*)d_in[6];
    const float* att1  = (const float*)d_in[7];
    const float* bias1 = (const float*)d_in[8];
    const float* Wl2   = (const float*)d_in[9];
    const float* bl2   = (const float*)d_in[10];
    const float* Wr2   = (const float*)d_in[11];
    const float* br2   = (const float*)d_in[12];
    const float* att2  = (const float*)d_in[13];
    const float* bias2 = (const float*)d_in[14];
    const float* Wlin  = (const float*)d_in[15];
    const float* blin  = (const float*)d_in[16];
    float* out = (float*)d_out;

    const int* src = ei;
    const int* dst = ei + NE;

    __nv_bfloat16 *xhi, *xlo, *h1hi, *h1lo, *h2hi, *h2lo;
    __nv_bfloat16 *wt1hi, *wt1lo, *wt2hi, *wt2lo, *wtlhi, *wtllo;
    float *xlr1, *xlr2, *cb1, *cb2;
    cudaGetSymbolAddress((void**)&xhi, g_xhi);
    cudaGetSymbolAddress((void**)&xlo, g_xlo);
    cudaGetSymbolAddress((void**)&h1hi, g_h1hi);
    cudaGetSymbolAddress((void**)&h1lo, g_h1lo);
    cudaGetSymbolAddress((void**)&h2hi, g_h2hi);
    cudaGetSymbolAddress((void**)&h2lo, g_h2lo);
    cudaGetSymbolAddress((void**)&wt1hi, g_wt1hi);
    cudaGetSymbolAddress((void**)&wt1lo, g_wt1lo);
    cudaGetSymbolAddress((void**)&wt2hi, g_wt2hi);
    cudaGetSymbolAddress((void**)&wt2lo, g_wt2lo);
    cudaGetSymbolAddress((void**)&wtlhi, g_wtlhi);
    cudaGetSymbolAddress((void**)&wtllo, g_wtllo);
    cudaGetSymbolAddress((void**)&xlr1, g_xlr1);
    cudaGetSymbolAddress((void**)&xlr2, g_xlr2);
    cudaGetSymbolAddress((void**)&cb1, g_cb1);
    cudaGetSymbolAddress((void**)&cb2, g_cb2);

    constexpr int SMEM128 = 2 * (2 * 128 * 40 + 2 * 128 * 40) * 2;
    constexpr int SMEM64  = 2 * (2 * 128 * 40 + 2 * 64 * 40) * 2;
    static cudaStream_t s_aux = nullptr;
    static cudaEvent_t e_fork = nullptr, e_csr = nullptr;
    if (!s_aux) {
        cudaFuncSetAttribute(gemm_bf16<128>, cudaFuncAttributeMaxDynamicSharedMemorySize, SMEM128);
        cudaFuncSetAttribute(gemm_bf16<64>,  cudaFuncAttributeMaxDynamicSharedMemorySize, SMEM64);
        cudaStreamCreateWithFlags(&s_aux, cudaStreamNonBlocking);
        cudaEventCreateWithFlags(&e_fork, cudaEventDisableTiming);
        cudaEventCreateWithFlags(&e_csr, cudaEventDisableTiming);
    }

    const int MB = (NN + 127) / 128;  // 157

    // #1: fused prep
    k_prep<<<(PREP_TOTAL + 255) / 256, 256>>>(x, Wl1, Wr1, Wl2, Wr2, Wlin, bl1, br1, bl2, br2);

    // fork CSR build onto side stream
    cudaEventRecord(e_fork, 0);
    cudaStreamWaitEvent(s_aux, e_fork, 0);
    k_hist<<<(NE + 255) / 256, 256, 0, s_aux>>>(dst);                 // #2
    k_scan<<<1, 1024, 0, s_aux>>>();                                  // #3

    // #4 (profiled slot): layer-1 GEMM
    gemm_bf16<128><<<dim3(2, MB), 256, SMEM128>>>(xhi, xlo, wt1hi, wt1lo, cb1, xlr1, NN, 256, 128);

    k_scatter<<<(NE + 255) / 256, 256, 0, s_aux>>>(src, dst);         // #5
    cudaEventRecord(e_csr, s_aux);
    cudaStreamWaitEvent(0, e_csr, 0);

    k_agg<128><<<NN / 8, 256>>>(xlr1, 256, 128, att1, bias1, h1hi, h1lo);
    gemm_bf16<128><<<dim3(8, MB), 256, SMEM128>>>(h1hi, h1lo, wt2hi, wt2lo, cb2, xlr2, NN, 1024, 128);
    k_agg<512><<<NN / 8, 256>>>(xlr2, 1024, 512, att2, bias2, h2hi, h2lo);
    gemm_bf16<64><<<dim3(1, MB), 256, SMEM64>>>(h2hi, h2lo, wtlhi, wtllo, blin, out, NN, 64, 512);
}

// round 8
// speedup vs baseline: 2.5057x; 1.1504x over previous
#include <cuda_runtime.h>
#include <cuda_bf16.h>
#include <cstdint>

#define NN 20000
#define NE 160000

// ---------------- scratch (device globals: allocation-free) ----------------
__device__ __nv_bfloat16 g_xhi[NN * 128], g_xlo[NN * 128];
__device__ float g_xlr1[NN * 256];
__device__ __nv_bfloat16 g_h1hi[NN * 128], g_h1lo[NN * 128];
__device__ float g_xlr2[NN * 1024];
__device__ __nv_bfloat16 g_h2hi[NN * 512], g_h2lo[NN * 512];
__device__ __nv_bfloat16 g_wt1hi[256 * 128],  g_wt1lo[256 * 128];
__device__ __nv_bfloat16 g_wt2hi[1024 * 128], g_wt2lo[1024 * 128];
__device__ __nv_bfloat16 g_wtlhi[64 * 512],   g_wtllo[64 * 512];
__device__ float g_cb1[256];
__device__ float g_cb2[1024];
__device__ int g_deg[NN];
__device__ int g_rowptr[NN + 1];
__device__ int g_cursor[NN];
__device__ int g_col[NE];

// ---------------- helpers ----------------
__device__ __forceinline__ uint32_t smem_u32(const void* p) {
    uint32_t a;
    asm("{ .reg .u64 t; cvta.to.shared.u64 t, %1; cvt.u32.u64 %0, t; }" : "=r"(a) : "l"(p));
    return a;
}
__device__ __forceinline__ void cp_async16(uint32_t dst, const void* src, bool pred) {
    int sz = pred ? 16 : 0;
    asm volatile("cp.async.cg.shared.global [%0], [%1], 16, %2;"
                 :: "r"(dst), "l"(src), "r"(sz) : "memory");
}
__device__ __forceinline__ void cp_commit() {
    asm volatile("cp.async.commit_group;" ::: "memory");
}
template <int W> __device__ __forceinline__ void cp_wait() {
    asm volatile("cp.async.wait_group %0;" :: "n"(W) : "memory");
}
__device__ __forceinline__ void split1(float a, __nv_bfloat16& h, __nv_bfloat16& l) {
    h = __float2bfloat16(a);
    l = __float2bfloat16(a - __bfloat162float(h));
}
__device__ __forceinline__ void mma_bf16(float* c, const uint32_t* a, const uint32_t* b) {
    asm volatile("mma.sync.aligned.m16n8k16.row.col.f32.bf16.bf16.f32 "
                 "{%0,%1,%2,%3}, {%4,%5,%6,%7}, {%8,%9}, {%0,%1,%2,%3};"
                 : "+f"(c[0]), "+f"(c[1]), "+f"(c[2]), "+f"(c[3])
                 : "r"(a[0]), "r"(a[1]), "r"(a[2]), "r"(a[3]), "r"(b[0]), "r"(b[1]));
}
__device__ __forceinline__ void ldsm_x4(uint32_t* r, uint32_t addr) {
    asm volatile("ldmatrix.sync.aligned.m8n8.x4.shared.b16 {%0,%1,%2,%3}, [%4];"
                 : "=r"(r[0]), "=r"(r[1]), "=r"(r[2]), "=r"(r[3]) : "r"(addr));
}

// ---------------- fused prep: zero_deg + x split + W transposes + bias -----
__global__ void k_prep(const float* __restrict__ x,
                       const float* __restrict__ Wl1, const float* __restrict__ Wr1,
                       const float* __restrict__ Wl2, const float* __restrict__ Wr2,
                       const float* __restrict__ Wlin,
                       const float* __restrict__ bl1, const float* __restrict__ br1,
                       const float* __restrict__ bl2, const float* __restrict__ br2) {
    const int S0 = NN;
    const int S1 = S0 + NN * 128;
    const int S2 = S1 + 16384;
    const int S3 = S2 + 16384;
    const int S4 = S3 + 65536;
    const int S5 = S4 + 65536;
    const int S6 = S5 + 32768;
    const int S7 = S6 + 1280;
    int i = blockIdx.x * blockDim.x + threadIdx.x;
    if (i < S0) {
        g_deg[i] = 0;
    } else if (i < S1) {
        int j = i - S0;
        __nv_bfloat16 h, l;
        split1(x[j], h, l);
        g_xhi[j] = h; g_xlo[j] = l;
    } else if (i < S2) {
        int j = i - S1, k = j >> 7, n = j & 127;
        __nv_bfloat16 h, l;
        split1(Wl1[j], h, l);
        g_wt1hi[n * 128 + k] = h; g_wt1lo[n * 128 + k] = l;
    } else if (i < S3) {
        int j = i - S2, k = j >> 7, n = j & 127;
        __nv_bfloat16 h, l;
        split1(Wr1[j], h, l);
        g_wt1hi[128 * 128 + n * 128 + k] = h; g_wt1lo[128 * 128 + n * 128 + k] = l;
    } else if (i < S4) {
        int j = i - S3, k = j >> 9, n = j & 511;
        __nv_bfloat16 h, l;
        split1(Wl2[j], h, l);
        g_wt2hi[n * 128 + k] = h; g_wt2lo[n * 128 + k] = l;
    } else if (i < S5) {
        int j = i - S4, k = j >> 9, n = j & 511;
        __nv_bfloat16 h, l;
        split1(Wr2[j], h, l);
        g_wt2hi[512 * 128 + n * 128 + k] = h; g_wt2lo[512 * 128 + n * 128 + k] = l;
    } else if (i < S6) {
        int j = i - S5, k = j >> 6, n = j & 63;
        __nv_bfloat16 h, l;
        split1(Wlin[j], h, l);
        g_wtlhi[n * 512 + k] = h; g_wtllo[n * 512 + k] = l;
    } else if (i < S7) {
        int j = i - S6;
        if (j < 256) g_cb1[j] = (j < 128) ? bl1[j] : br1[j - 128];
        else {
            int b = j - 256;
            g_cb2[b] = (b < 512) ? bl2[b] : br2[b - 512];
        }
    }
}
#define PREP_TOTAL (NN + NN * 128 + 16384 * 2 + 65536 * 2 + 32768 + 1280)

// ---------------- CSR build (counting sort by dst) ----------------
__global__ void k_hist(const int* __restrict__ dst) {
    int e = blockIdx.x * blockDim.x + threadIdx.x;
    if (e < NE) atomicAdd(&g_deg[dst[e]], 1);
}
__global__ void k_scan() {
    __shared__ int s[1024];
    const int CH = (NN + 1023) / 1024;
    int t = threadIdx.x;
    int start = t * CH;
    int end = start + CH < NN ? start + CH : NN;
    int sum = 0;
    for (int i = start; i < end; i++) sum += g_deg[i];
    s[t] = sum;
    __syncthreads();
    for (int off = 1; off < 1024; off <<= 1) {
        int v = (t >= off) ? s[t - off] : 0;
        __syncthreads();
        s[t] += v;
        __syncthreads();
    }
    int run = (t == 0) ? 0 : s[t - 1];
    for (int i = start; i < end; i++) {
        g_rowptr[i] = run;
        g_cursor[i] = run;
        run += g_deg[i];
    }
    if (t == 1023) g_rowptr[NN] = s[1023];
}
__global__ void k_scatter(const int* __restrict__ src, const int* __restrict__ dst) {
    int e = blockIdx.x * blockDim.x + threadIdx.x;
    if (e < NE) {
        int d = dst[e];
        int pos = atomicAdd(&g_cursor[d], 1);
        g_col[pos] = src[e];
    }
}

// ---------------- pipelined bf16-split GEMM: M-tile 64, 3 CTAs/SM ---------
// 8 warps in 2(M) x 4(N); warp tile 32 x BN/4. BK=32, 2-stage cp.async.
template <int BN>
__global__ void __launch_bounds__(256, 3)
gemm_bf16(const __nv_bfloat16* __restrict__ Ahi, const __nv_bfloat16* __restrict__ Alo,
          const __nv_bfloat16* __restrict__ Bhi, const __nv_bfloat16* __restrict__ Blo,
          const float* __restrict__ bias, float* __restrict__ C,
          int M, int N, int K) {
    constexpr int BM = 64;
    constexpr int BK = 32;
    constexpr int STR = 40;
    constexpr int ASZ = BM * STR;
    constexpr int BSZ = BN * STR;
    constexpr int STAGE = 2 * ASZ + 2 * BSZ;
    constexpr int NT = BN / 32;
    extern __shared__ __nv_bfloat16 sm[];

    const int tid = threadIdx.x;
    const int wid = tid >> 5;
    const int lane = tid & 31;
    const int wm = wid & 1;
    const int wn = wid >> 1;
    const int gid = lane >> 2;
    const int tig = lane & 3;
    const int m0 = blockIdx.y * BM;
    const int n0 = blockIdx.x * BN;
    const int nk = K / BK;

    const int a_row = wm * 32 + (lane & 7) + ((lane >> 3) & 1) * 8;
    const int a_koff = (lane & 16) >> 1;
    const int b_row = wn * (NT * 8) + (lane & 7) + ((lane & 16) >> 1);
    const int b_koff = lane & 8;

    float c[2][NT][4];
#pragma unroll
    for (int mt = 0; mt < 2; mt++)
#pragma unroll
        for (int nt = 0; nt < NT; nt++)
#pragma unroll
            for (int r = 0; r < 4; r++) c[mt][nt][r] = 0.f;

    auto load_stage = [&](int kc, int s) {
        const int k0 = kc * BK;
        __nv_bfloat16* base = sm + s * STAGE;
        // A hi/lo: 64 rows x 4 chunks (16B) = 256 items
        {
            int row = tid >> 2, ch = tid & 3;
            int gm = m0 + row;
            bool p = gm < M;
            int gmc = p ? gm : (M - 1);
            size_t goff = (size_t)gmc * K + k0 + ch * 8;
            uint32_t d = smem_u32(base + row * STR + ch * 8);
            cp_async16(d, Ahi + goff, p);
            cp_async16(d + ASZ * 2, Alo + goff, p);
        }
        // B hi/lo: BN rows x 4 chunks
#pragma unroll
        for (int j = 0; j < BN / 64; j++) {
            int i = tid + j * 256;
            int row = i >> 2, ch = i & 3;
            size_t goff = (size_t)(n0 + row) * K + k0 + ch * 8;
            uint32_t d = smem_u32(base + 2 * ASZ + row * STR + ch * 8);
            cp_async16(d, Bhi + goff, true);
            cp_async16(d + BSZ * 2, Blo + goff, true);
        }
    };

    load_stage(0, 0);
    cp_commit();

    for (int kc = 0; kc < nk; kc++) {
        const int s = kc & 1;
        if (kc + 1 < nk) {
            load_stage(kc + 1, s ^ 1);
            cp_commit();
            cp_wait<1>();
        } else {
            cp_wait<0>();
        }
        __syncthreads();

        const uint32_t stg = smem_u32(sm + s * STAGE);
        const uint32_t ah_base = stg + (a_row * STR + a_koff) * 2;
        const uint32_t al_base = ah_base + ASZ * 2;
        const uint32_t bh_base = stg + 2 * ASZ * 2 + (b_row * STR + b_koff) * 2;
        const uint32_t bl_base = bh_base + BSZ * 2;

#pragma unroll
        for (int kb = 0; kb < BK; kb += 16) {
            uint32_t bfh[NT][2], bfl[NT][2];
#pragma unroll
            for (int p = 0; p < NT / 2; p++) {
                uint32_t off = (p * 16 * STR + kb) * 2;
                ldsm_x4(&bfh[2 * p][0], bh_base + off);
                ldsm_x4(&bfl[2 * p][0], bl_base + off);
            }
#pragma unroll
            for (int mt = 0; mt < 2; mt++) {
                uint32_t afh[4], afl[4];
                uint32_t off = (mt * 16 * STR + kb) * 2;
                ldsm_x4(afh, ah_base + off);
                ldsm_x4(afl, al_base + off);
#pragma unroll
                for (int nt = 0; nt < NT; nt++) {
                    mma_bf16(c[mt][nt], afh, bfh[nt]);
                    mma_bf16(c[mt][nt], afh, bfl[nt]);
                    mma_bf16(c[mt][nt], afl, bfh[nt]);
                }
            }
        }
        __syncthreads();
    }

#pragma unroll
    for (int mt = 0; mt < 2; mt++) {
        int r0 = m0 + wm * 32 + mt * 16 + gid;
#pragma unroll
        for (int nt = 0; nt < NT; nt++) {
            int col = n0 + wn * (NT * 8) + nt * 8 + tig * 2;
            float b0 = bias[col], b1 = bias[col + 1];
            if (r0 < M) {
                float2 v0 = make_float2(c[mt][nt][0] + b0, c[mt][nt][1] + b1);
                *reinterpret_cast<float2*>(C + (size_t)r0 * N + col) = v0;
            }
            if (r0 + 8 < M) {
                float2 v1 = make_float2(c[mt][nt][2] + b0, c[mt][nt][3] + b1);
                *reinterpret_cast<float2*>(C + (size_t)(r0 + 8) * N + col) = v1;
            }
        }
    }
}

// ---------------- fused GATv2 edge-softmax + aggregation -------------------
// NWPN warps cooperate per node; each warp owns D/NWPN contiguous channels
// (whole heads). Head-group score reduction spans LPH = 8*NWPN lanes.
template <int D, int NWPN>
__global__ void __launch_bounds__(256, 3)
k_agg(const float* __restrict__ xlr, int SR, int XO,
      const float* __restrict__ att, const float* __restrict__ bias,
      __nv_bfloat16* __restrict__ ohi, __nv_bfloat16* __restrict__ olo) {
    constexpr int CPL = D / (32 * NWPN);
    constexpr int V = CPL / 4;
    constexpr int LPH = 8 * NWPN;   // lanes per head group

    int gw = (blockIdx.x * blockDim.x + threadIdx.x) >> 5;
    int lane = threadIdx.x & 31;
    int node = gw / NWPN;
    int part = gw % NWPN;
    if (node >= NN) return;
    const int base = part * (D / NWPN) + lane * CPL;

    float attv[CPL], xrv[CPL];
#pragma unroll
    for (int j = 0; j < V; j++) {
        float4 a4 = *reinterpret_cast<const float4*>(att + base + 4 * j);
        float4 r4 = *reinterpret_cast<const float4*>(xlr + (size_t)node * SR + XO + base + 4 * j);
        attv[4 * j + 0] = a4.x; attv[4 * j + 1] = a4.y;
        attv[4 * j + 2] = a4.z; attv[4 * j + 3] = a4.w;
        xrv[4 * j + 0] = r4.x; xrv[4 * j + 1] = r4.y;
        xrv[4 * j + 2] = r4.z; xrv[4 * j + 3] = r4.w;
    }

    float m = -3.402823466e38f;
    float ssum = 0.f;
    float acc[CPL];
#pragma unroll
    for (int c = 0; c < CPL; c++) acc[c] = 0.f;

    const int rs = g_rowptr[node];
    const int re = g_rowptr[node + 1];

    if (rs < re) {
        int s = g_col[rs];
        float xlv[CPL];
#pragma unroll
        for (int j = 0; j < V; j++) {
            float4 v = *reinterpret_cast<const float4*>(xlr + (size_t)s * SR + base + 4 * j);
            xlv[4 * j + 0] = v.x; xlv[4 * j + 1] = v.y;
            xlv[4 * j + 2] = v.z; xlv[4 * j + 3] = v.w;
        }
        for (int p = rs; p < re; p++) {
            int sn = (p + 1 < re) ? g_col[p + 1] : s;
            float xln[CPL];
#pragma unroll
            for (int j = 0; j < V; j++) {
                float4 v = *reinterpret_cast<const float4*>(xlr + (size_t)sn * SR + base + 4 * j);
                xln[4 * j + 0] = v.x; xln[4 * j + 1] = v.y;
                xln[4 * j + 2] = v.z; xln[4 * j + 3] = v.w;
            }
            float partial = 0.f;
#pragma unroll
            for (int c = 0; c < CPL; c++) {
                float e = xlv[c] + xrv[c];
                e = (e >= 0.f) ? e : 0.2f * e;
                partial = fmaf(attv[c], e, partial);
            }
#pragma unroll
            for (int off = 1; off < LPH; off <<= 1)
                partial += __shfl_xor_sync(0xffffffffu, partial, off);

            float mnew = fmaxf(m, partial);
            float fac = __expf(m - mnew);
            float w = __expf(partial - mnew);
            ssum = ssum * fac + w;
#pragma unroll
            for (int c = 0; c < CPL; c++) acc[c] = fmaf(acc[c], fac, w * xlv[c]);
            m = mnew;
#pragma unroll
            for (int c = 0; c < CPL; c++) xlv[c] = xln[c];
        }
    }

    float inv = (ssum > 0.f) ? (1.f / ssum) : 0.f;
#pragma unroll
    for (int j = 0; j < CPL / 2; j++) {
        float v0 = fmaxf(fmaf(acc[2 * j], inv, bias[base + 2 * j]), 0.f);
        float v1 = fmaxf(fmaf(acc[2 * j + 1], inv, bias[base + 2 * j + 1]), 0.f);
        __nv_bfloat16 h0, l0, h1, l1;
        split1(v0, h0, l0);
        split1(v1, h1, l1);
        __nv_bfloat162 hp = __halves2bfloat162(h0, h1);
        __nv_bfloat162 lp = __halves2bfloat162(l0, l1);
        *reinterpret_cast<__nv_bfloat162*>(ohi + (size_t)node * D + base + 2 * j) = hp;
        *reinterpret_cast<__nv_bfloat162*>(olo + (size_t)node * D + base + 2 * j) = lp;
    }
}

// ---------------- launch ----------------
extern "C" void kernel_launch(void* const* d_in, const int* in_sizes, int n_in,
                              void* d_out, int out_size) {
    (void)in_sizes; (void)n_in; (void)out_size;
    const float* x     = (const float*)d_in[0];
    const int*   ei    = (const int*)  d_in[1];
    const float* Wl1   = (const float*)d_in[3];
    const float* bl1   = (const float*)d_in[4];
    const float* Wr1   = (const float*)d_in[5];
    const float* br1   = (const float*)d_in[6];
    const float* att1  = (const float*)d_in[7];
    const float* bias1 = (const float*)d_in[8];
    const float* Wl2   = (const float*)d_in[9];
    const float* bl2   = (const float*)d_in[10];
    const float* Wr2   = (const float*)d_in[11];
    const float* br2   = (const float*)d_in[12];
    const float* att2  = (const float*)d_in[13];
    const float* bias2 = (const float*)d_in[14];
    const float* Wlin  = (const float*)d_in[15];
    const float* blin  = (const float*)d_in[16];
    float* out = (float*)d_out;

    const int* src = ei;
    const int* dst = ei + NE;

    __nv_bfloat16 *xhi, *xlo, *h1hi, *h1lo, *h2hi, *h2lo;
    __nv_bfloat16 *wt1hi, *wt1lo, *wt2hi, *wt2lo, *wtlhi, *wtllo;
    float *xlr1, *xlr2, *cb1, *cb2;
    cudaGetSymbolAddress((void**)&xhi, g_xhi);
    cudaGetSymbolAddress((void**)&xlo, g_xlo);
    cudaGetSymbolAddress((void**)&h1hi, g_h1hi);
    cudaGetSymbolAddress((void**)&h1lo, g_h1lo);
    cudaGetSymbolAddress((void**)&h2hi, g_h2hi);
    cudaGetSymbolAddress((void**)&h2lo, g_h2lo);
    cudaGetSymbolAddress((void**)&wt1hi, g_wt1hi);
    cudaGetSymbolAddress((void**)&wt1lo, g_wt1lo);
    cudaGetSymbolAddress((void**)&wt2hi, g_wt2hi);
    cudaGetSymbolAddress((void**)&wt2lo, g_wt2lo);
    cudaGetSymbolAddress((void**)&wtlhi, g_wtlhi);
    cudaGetSymbolAddress((void**)&wtllo, g_wtllo);
    cudaGetSymbolAddress((void**)&xlr1, g_xlr1);
    cudaGetSymbolAddress((void**)&xlr2, g_xlr2);
    cudaGetSymbolAddress((void**)&cb1, g_cb1);
    cudaGetSymbolAddress((void**)&cb2, g_cb2);

    constexpr int SMEM128 = 2 * (2 * 64 * 40 + 2 * 128 * 40) * 2;  // 61440 B
    constexpr int SMEM64  = 2 * (2 * 64 * 40 + 2 * 64 * 40) * 2;   // 40960 B
    static cudaStream_t s_aux = nullptr;
    static cudaEvent_t e_fork = nullptr, e_csr = nullptr;
    if (!s_aux) {
        cudaFuncSetAttribute(gemm_bf16<128>, cudaFuncAttributeMaxDynamicSharedMemorySize, SMEM128);
        cudaFuncSetAttribute(gemm_bf16<64>,  cudaFuncAttributeMaxDynamicSharedMemorySize, SMEM64);
        cudaStreamCreateWithFlags(&s_aux, cudaStreamNonBlocking);
        cudaEventCreateWithFlags(&e_fork, cudaEventDisableTiming);
        cudaEventCreateWithFlags(&e_csr, cudaEventDisableTiming);
    }

    const int MB = (NN + 63) / 64;  // 313

    // #1: fused prep
    k_prep<<<(PREP_TOTAL + 255) / 256, 256>>>(x, Wl1, Wr1, Wl2, Wr2, Wlin, bl1, br1, bl2, br2);

    // fork CSR build onto side stream
    cudaEventRecord(e_fork, 0);
    cudaStreamWaitEvent(s_aux, e_fork, 0);
    k_hist<<<(NE + 255) / 256, 256, 0, s_aux>>>(dst);                 // #2
    k_scan<<<1, 1024, 0, s_aux>>>();                                  // #3

    // #4 (profiled slot): layer-1 GEMM (N=256 = [xl|xr])
    gemm_bf16<128><<<dim3(2, MB), 256, SMEM128>>>(xhi, xlo, wt1hi, wt1lo, cb1, xlr1, NN, 256, 128);

    k_scatter<<<(NE + 255) / 256, 256, 0, s_aux>>>(src, dst);         // #5
    cudaEventRecord(e_csr, s_aux);
    cudaStreamWaitEvent(0, e_csr, 0);

    k_agg<128, 1><<<(NN * 1 + 7) / 8, 256>>>(xlr1, 256, 128, att1, bias1, h1hi, h1lo);
    gemm_bf16<128><<<dim3(8, MB), 256, SMEM128>>>(h1hi, h1lo, wt2hi, wt2lo, cb2, xlr2, NN, 1024, 128);
    k_agg<512, 2><<<(NN * 2 + 7) / 8, 256>>>(xlr2, 1024, 512, att2, bias2, h2hi, h2lo);
    gemm_bf16<64><<<dim3(1, MB), 256, SMEM64>>>(h2hi, h2lo, wtlhi, wtllo, blin, out, NN, 64, 512);
}

// round 9
// speedup vs baseline: 2.8661x; 1.1438x over previous
#include <cuda_runtime.h>
#include <cuda_fp16.h>
#include <cstdint>

#define NN 20000
#define NE 160000

// ---------------- scratch (device globals: allocation-free) ----------------
__device__ __half g_xhi[NN * 128], g_xlo[NN * 128];
__device__ float g_xlr1[NN * 256];
__device__ __half g_h1hi[NN * 128], g_h1lo[NN * 128];
__device__ float g_xlr2[NN * 1024];
__device__ __half g_h2hi[NN * 512], g_h2lo[NN * 512];
__device__ __half g_wt1h[256 * 128];
__device__ __half g_wt2h[1024 * 128];
__device__ __half g_wtlh[64 * 512];
__device__ float g_cb1[256];
__device__ float g_cb2[1024];
__device__ int g_deg[NN];
__device__ int g_rowptr[NN + 1];
__device__ int g_cursor[NN];
__device__ int g_col[NE];

// ---------------- helpers ----------------
__device__ __forceinline__ uint32_t smem_u32(const void* p) {
    uint32_t a;
    asm("{ .reg .u64 t; cvta.to.shared.u64 t, %1; cvt.u32.u64 %0, t; }" : "=r"(a) : "l"(p));
    return a;
}
__device__ __forceinline__ void cp_async16(uint32_t dst, const void* src, bool pred) {
    int sz = pred ? 16 : 0;
    asm volatile("cp.async.cg.shared.global [%0], [%1], 16, %2;"
                 :: "r"(dst), "l"(src), "r"(sz) : "memory");
}
__device__ __forceinline__ void cp_commit() {
    asm volatile("cp.async.commit_group;" ::: "memory");
}
template <int W> __device__ __forceinline__ void cp_wait() {
    asm volatile("cp.async.wait_group %0;" :: "n"(W) : "memory");
}
__device__ __forceinline__ void split1h(float a, __half& h, __half& l) {
    h = __float2half_rn(a);
    l = __float2half_rn(a - __half2float(h));
}
__device__ __forceinline__ void mma_f16(float* c, const uint32_t* a, const uint32_t* b) {
    asm volatile("mma.sync.aligned.m16n8k16.row.col.f32.f16.f16.f32 "
                 "{%0,%1,%2,%3}, {%4,%5,%6,%7}, {%8,%9}, {%0,%1,%2,%3};"
                 : "+f"(c[0]), "+f"(c[1]), "+f"(c[2]), "+f"(c[3])
                 : "r"(a[0]), "r"(a[1]), "r"(a[2]), "r"(a[3]), "r"(b[0]), "r"(b[1]));
}
__device__ __forceinline__ void ldsm_x4(uint32_t* r, uint32_t addr) {
    asm volatile("ldmatrix.sync.aligned.m8n8.x4.shared.b16 {%0,%1,%2,%3}, [%4];"
                 : "=r"(r[0]), "=r"(r[1]), "=r"(r[2]), "=r"(r[3]) : "r"(addr));
}

// ---------------- fused prep: zero_deg + x split + W transposes + bias -----
__global__ void k_prep(const float* __restrict__ x,
                       const float* __restrict__ Wl1, const float* __restrict__ Wr1,
                       const float* __restrict__ Wl2, const float* __restrict__ Wr2,
                       const float* __restrict__ Wlin,
                       const float* __restrict__ bl1, const float* __restrict__ br1,
                       const float* __restrict__ bl2, const float* __restrict__ br2) {
    const int S0 = NN;
    const int S1 = S0 + NN * 128;
    const int S2 = S1 + 16384;
    const int S3 = S2 + 16384;
    const int S4 = S3 + 65536;
    const int S5 = S4 + 65536;
    const int S6 = S5 + 32768;
    const int S7 = S6 + 1280;
    int i = blockIdx.x * blockDim.x + threadIdx.x;
    if (i < S0) {
        g_deg[i] = 0;
    } else if (i < S1) {
        int j = i - S0;
        __half h, l;
        split1h(x[j], h, l);
        g_xhi[j] = h; g_xlo[j] = l;
    } else if (i < S2) {
        int j = i - S1, k = j >> 7, n = j & 127;
        g_wt1h[n * 128 + k] = __float2half_rn(Wl1[j]);
    } else if (i < S3) {
        int j = i - S2, k = j >> 7, n = j & 127;
        g_wt1h[128 * 128 + n * 128 + k] = __float2half_rn(Wr1[j]);
    } else if (i < S4) {
        int j = i - S3, k = j >> 9, n = j & 511;
        g_wt2h[n * 128 + k] = __float2half_rn(Wl2[j]);
    } else if (i < S5) {
        int j = i - S4, k = j >> 9, n = j & 511;
        g_wt2h[512 * 128 + n * 128 + k] = __float2half_rn(Wr2[j]);
    } else if (i < S6) {
        int j = i - S5, k = j >> 6, n = j & 63;
        g_wtlh[n * 512 + k] = __float2half_rn(Wlin[j]);
    } else if (i < S7) {
        int j = i - S6;
        if (j < 256) g_cb1[j] = (j < 128) ? bl1[j] : br1[j - 128];
        else {
            int b = j - 256;
            g_cb2[b] = (b < 512) ? bl2[b] : br2[b - 512];
        }
    }
}
#define PREP_TOTAL (NN + NN * 128 + 16384 * 2 + 65536 * 2 + 32768 + 1280)

// ---------------- CSR build (counting sort by dst) ----------------
__global__ void k_hist(const int* __restrict__ dst) {
    int e = blockIdx.x * blockDim.x + threadIdx.x;
    if (e < NE) atomicAdd(&g_deg[dst[e]], 1);
}
__global__ void k_scan() {
    __shared__ int s[1024];
    const int CH = (NN + 1023) / 1024;
    int t = threadIdx.x;
    int start = t * CH;
    int end = start + CH < NN ? start + CH : NN;
    int sum = 0;
    for (int i = start; i < end; i++) sum += g_deg[i];
    s[t] = sum;
    __syncthreads();
    for (int off = 1; off < 1024; off <<= 1) {
        int v = (t >= off) ? s[t - off] : 0;
        __syncthreads();
        s[t] += v;
        __syncthreads();
    }
    int run = (t == 0) ? 0 : s[t - 1];
    for (int i = start; i < end; i++) {
        g_rowptr[i] = run;
        g_cursor[i] = run;
        run += g_deg[i];
    }
    if (t == 1023) g_rowptr[NN] = s[1023];
}
__global__ void k_scatter(const int* __restrict__ src, const int* __restrict__ dst) {
    int e = blockIdx.x * blockDim.x + threadIdx.x;
    if (e < NE) {
        int d = dst[e];
        int pos = atomicAdd(&g_cursor[d], 1);
        g_col[pos] = src[e];
    }
}

// ---------------- pipelined fp16 2-MMA split GEMM -------------------------
// C = (Ah + Al)[M,K] @ Bh[N,K]^T + bias  (drops Ah*Bl, ~2^-12 relative).
// M-tile 64, BK=32, 2-stage cp.async, 8 warps (2M x 4N), 3 CTAs/SM.
template <int BN>
__global__ void __launch_bounds__(256, 3)
gemm_f16(const __half* __restrict__ Ahi, const __half* __restrict__ Alo,
         const __half* __restrict__ Bh, const float* __restrict__ bias,
         float* __restrict__ C, int M, int N, int K) {
    constexpr int BM = 64;
    constexpr int BK = 32;
    constexpr int STR = 40;
    constexpr int ASZ = BM * STR;             // elems (per A buffer)
    constexpr int BSZ = BN * STR;
    constexpr int STAGE = 2 * ASZ + BSZ;      // Ah + Al + Bh
    constexpr int NT = BN / 32;
    extern __shared__ __half sm[];

    const int tid = threadIdx.x;
    const int wid = tid >> 5;
    const int lane = tid & 31;
    const int wm = wid & 1;
    const int wn = wid >> 1;
    const int gid = lane >> 2;
    const int tig = lane & 3;
    const int m0 = blockIdx.y * BM;
    const int n0 = blockIdx.x * BN;
    const int nk = K / BK;

    const int a_row = wm * 32 + (lane & 7) + ((lane >> 3) & 1) * 8;
    const int a_koff = (lane & 16) >> 1;
    const int b_row = wn * (NT * 8) + (lane & 7) + ((lane & 16) >> 1);
    const int b_koff = lane & 8;

    float c[2][NT][4];
#pragma unroll
    for (int mt = 0; mt < 2; mt++)
#pragma unroll
        for (int nt = 0; nt < NT; nt++)
#pragma unroll
            for (int r = 0; r < 4; r++) c[mt][nt][r] = 0.f;

    auto load_stage = [&](int kc, int s) {
        const int k0 = kc * BK;
        __half* base = sm + s * STAGE;
        // A hi/lo: 64 rows x 4 chunks (16B) = 256 items
        {
            int row = tid >> 2, ch = tid & 3;
            int gm = m0 + row;
            bool p = gm < M;
            int gmc = p ? gm : (M - 1);
            size_t goff = (size_t)gmc * K + k0 + ch * 8;
            uint32_t d = smem_u32(base + row * STR + ch * 8);
            cp_async16(d, Ahi + goff, p);
            cp_async16(d + ASZ * 2, Alo + goff, p);
        }
        // B hi: BN rows x 4 chunks
#pragma unroll
        for (int j = 0; j < BN / 64; j++) {
            int i = tid + j * 256;
            int row = i >> 2, ch = i & 3;
            size_t goff = (size_t)(n0 + row) * K + k0 + ch * 8;
            uint32_t d = smem_u32(base + 2 * ASZ + row * STR + ch * 8);
            cp_async16(d, Bh + goff, true);
        }
    };

    load_stage(0, 0);
    cp_commit();

    for (int kc = 0; kc < nk; kc++) {
        const int s = kc & 1;
        if (kc + 1 < nk) {
            load_stage(kc + 1, s ^ 1);
            cp_commit();
            cp_wait<1>();
        } else {
            cp_wait<0>();
        }
        __syncthreads();

        const uint32_t stg = smem_u32(sm + s * STAGE);
        const uint32_t ah_base = stg + (a_row * STR + a_koff) * 2;
        const uint32_t al_base = ah_base + ASZ * 2;
        const uint32_t bh_base = stg + 2 * ASZ * 2 + (b_row * STR + b_koff) * 2;

#pragma unroll
        for (int kb = 0; kb < BK; kb += 16) {
            uint32_t bfh[NT][2];
#pragma unroll
            for (int p = 0; p < NT / 2; p++) {
                uint32_t off = (p * 16 * STR + kb) * 2;
                ldsm_x4(&bfh[2 * p][0], bh_base + off);
            }
#pragma unroll
            for (int mt = 0; mt < 2; mt++) {
                uint32_t afh[4], afl[4];
                uint32_t off = (mt * 16 * STR + kb) * 2;
                ldsm_x4(afh, ah_base + off);
                ldsm_x4(afl, al_base + off);
#pragma unroll
                for (int nt = 0; nt < NT; nt++) {
                    mma_f16(c[mt][nt], afh, bfh[nt]);   // Ah*Bh
                    mma_f16(c[mt][nt], afl, bfh[nt]);   // Al*Bh
                }
            }
        }
        __syncthreads();
    }

#pragma unroll
    for (int mt = 0; mt < 2; mt++) {
        int r0 = m0 + wm * 32 + mt * 16 + gid;
#pragma unroll
        for (int nt = 0; nt < NT; nt++) {
            int col = n0 + wn * (NT * 8) + nt * 8 + tig * 2;
            float b0 = bias[col], b1 = bias[col + 1];
            if (r0 < M) {
                float2 v0 = make_float2(c[mt][nt][0] + b0, c[mt][nt][1] + b1);
                *reinterpret_cast<float2*>(C + (size_t)r0 * N + col) = v0;
            }
            if (r0 + 8 < M) {
                float2 v1 = make_float2(c[mt][nt][2] + b0, c[mt][nt][3] + b1);
                *reinterpret_cast<float2*>(C + (size_t)(r0 + 8) * N + col) = v1;
            }
        }
    }
}

// ---------------- fused GATv2 edge-softmax + aggregation -------------------
// NWPN warps cooperate per node; each warp owns D/NWPN contiguous channels.
template <int D, int NWPN>
__global__ void __launch_bounds__(256, 3)
k_agg(const float* __restrict__ xlr, int SR, int XO,
      const float* __restrict__ att, const float* __restrict__ bias,
      __half* __restrict__ ohi, __half* __restrict__ olo) {
    constexpr int CPL = D / (32 * NWPN);
    constexpr int V = CPL / 4;
    constexpr int LPH = 8 * NWPN;

    int gw = (blockIdx.x * blockDim.x + threadIdx.x) >> 5;
    int lane = threadIdx.x & 31;
    int node = gw / NWPN;
    int part = gw % NWPN;
    if (node >= NN) return;
    const int base = part * (D / NWPN) + lane * CPL;

    float attv[CPL], xrv[CPL];
#pragma unroll
    for (int j = 0; j < V; j++) {
        float4 a4 = *reinterpret_cast<const float4*>(att + base + 4 * j);
        float4 r4 = *reinterpret_cast<const float4*>(xlr + (size_t)node * SR + XO + base + 4 * j);
        attv[4 * j + 0] = a4.x; attv[4 * j + 1] = a4.y;
        attv[4 * j + 2] = a4.z; attv[4 * j + 3] = a4.w;
        xrv[4 * j + 0] = r4.x; xrv[4 * j + 1] = r4.y;
        xrv[4 * j + 2] = r4.z; xrv[4 * j + 3] = r4.w;
    }

    float m = -3.402823466e38f;
    float ssum = 0.f;
    float acc[CPL];
#pragma unroll
    for (int c = 0; c < CPL; c++) acc[c] = 0.f;

    const int rs = g_rowptr[node];
    const int re = g_rowptr[node + 1];

    if (rs < re) {
        int s = g_col[rs];
        float xlv[CPL];
#pragma unroll
        for (int j = 0; j < V; j++) {
            float4 v = *reinterpret_cast<const float4*>(xlr + (size_t)s * SR + base + 4 * j);
            xlv[4 * j + 0] = v.x; xlv[4 * j + 1] = v.y;
            xlv[4 * j + 2] = v.z; xlv[4 * j + 3] = v.w;
        }
        for (int p = rs; p < re; p++) {
            int sn = (p + 1 < re) ? g_col[p + 1] : s;
            float xln[CPL];
#pragma unroll
            for (int j = 0; j < V; j++) {
                float4 v = *reinterpret_cast<const float4*>(xlr + (size_t)sn * SR + base + 4 * j);
                xln[4 * j + 0] = v.x; xln[4 * j + 1] = v.y;
                xln[4 * j + 2] = v.z; xln[4 * j + 3] = v.w;
            }
            float partial = 0.f;
#pragma unroll
            for (int c = 0; c < CPL; c++) {
                float e = xlv[c] + xrv[c];
                e = (e >= 0.f) ? e : 0.2f * e;
                partial = fmaf(attv[c], e, partial);
            }
#pragma unroll
            for (int off = 1; off < LPH; off <<= 1)
                partial += __shfl_xor_sync(0xffffffffu, partial, off);

            float mnew = fmaxf(m, partial);
            float fac = __expf(m - mnew);
            float w = __expf(partial - mnew);
            ssum = ssum * fac + w;
#pragma unroll
            for (int c = 0; c < CPL; c++) acc[c] = fmaf(acc[c], fac, w * xlv[c]);
            m = mnew;
#pragma unroll
            for (int c = 0; c < CPL; c++) xlv[c] = xln[c];
        }
    }

    float inv = (ssum > 0.f) ? (1.f / ssum) : 0.f;
#pragma unroll
    for (int j = 0; j < CPL / 2; j++) {
        float v0 = fmaxf(fmaf(acc[2 * j], inv, bias[base + 2 * j]), 0.f);
        float v1 = fmaxf(fmaf(acc[2 * j + 1], inv, bias[base + 2 * j + 1]), 0.f);
        __half h0, l0, h1, l1;
        split1h(v0, h0, l0);
        split1h(v1, h1, l1);
        __half2 hp = __halves2half2(h0, h1);
        __half2 lp = __halves2half2(l0, l1);
        *reinterpret_cast<__half2*>(ohi + (size_t)node * D + base + 2 * j) = hp;
        *reinterpret_cast<__half2*>(olo + (size_t)node * D + base + 2 * j) = lp;
    }
}

// ---------------- launch ----------------
extern "C" void kernel_launch(void* const* d_in, const int* in_sizes, int n_in,
                              void* d_out, int out_size) {
    (void)in_sizes; (void)n_in; (void)out_size;
    const float* x     = (const float*)d_in[0];
    const int*   ei    = (const int*)  d_in[1];
    const float* Wl1   = (const float*)d_in[3];
    const float* bl1   = (const float*)d_in[4];
    const float* Wr1   = (const float*)d_in[5];
    const float* br1   = (const float*)d_in[6];
    const float* att1  = (const float*)d_in[7];
    const float* bias1 = (const float*)d_in[8];
    const float* Wl2   = (const float*)d_in[9];
    const float* bl2   = (const float*)d_in[10];
    const float* Wr2   = (const float*)d_in[11];
    const float* br2   = (const float*)d_in[12];
    const float* att2  = (const float*)d_in[13];
    const float* bias2 = (const float*)d_in[14];
    const float* Wlin  = (const float*)d_in[15];
    const float* blin  = (const float*)d_in[16];
    float* out = (float*)d_out;

    const int* src = ei;
    const int* dst = ei + NE;

    __half *xhi, *xlo, *h1hi, *h1lo, *h2hi, *h2lo;
    __half *wt1h, *wt2h, *wtlh;
    float *xlr1, *xlr2, *cb1, *cb2;
    cudaGetSymbolAddress((void**)&xhi, g_xhi);
    cudaGetSymbolAddress((void**)&xlo, g_xlo);
    cudaGetSymbolAddress((void**)&h1hi, g_h1hi);
    cudaGetSymbolAddress((void**)&h1lo, g_h1lo);
    cudaGetSymbolAddress((void**)&h2hi, g_h2hi);
    cudaGetSymbolAddress((void**)&h2lo, g_h2lo);
    cudaGetSymbolAddress((void**)&wt1h, g_wt1h);
    cudaGetSymbolAddress((void**)&wt2h, g_wt2h);
    cudaGetSymbolAddress((void**)&wtlh, g_wtlh);
    cudaGetSymbolAddress((void**)&xlr1, g_xlr1);
    cudaGetSymbolAddress((void**)&xlr2, g_xlr2);
    cudaGetSymbolAddress((void**)&cb1, g_cb1);
    cudaGetSymbolAddress((void**)&cb2, g_cb2);

    constexpr int SMEM128 = 2 * (2 * 64 * 40 + 128 * 40) * 2;  // 40960 B
    constexpr int SMEM64  = 2 * (2 * 64 * 40 + 64 * 40) * 2;   // 30720 B
    static cudaStream_t s_aux = nullptr;
    static cudaEvent_t e_fork = nullptr, e_csr = nullptr;
    if (!s_aux) {
        cudaFuncSetAttribute(gemm_f16<128>, cudaFuncAttributeMaxDynamicSharedMemorySize, SMEM128);
        cudaFuncSetAttribute(gemm_f16<64>,  cudaFuncAttributeMaxDynamicSharedMemorySize, SMEM64);
        cudaStreamCreateWithFlags(&s_aux, cudaStreamNonBlocking);
        cudaEventCreateWithFlags(&e_fork, cudaEventDisableTiming);
        cudaEventCreateWithFlags(&e_csr, cudaEventDisableTiming);
    }

    const int MB = (NN + 63) / 64;  // 313

    // #1: fused prep
    k_prep<<<(PREP_TOTAL + 255) / 256, 256>>>(x, Wl1, Wr1, Wl2, Wr2, Wlin, bl1, br1, bl2, br2);

    // fork CSR build onto side stream
    cudaEventRecord(e_fork, 0);
    cudaStreamWaitEvent(s_aux, e_fork, 0);
    k_hist<<<(NE + 255) / 256, 256, 0, s_aux>>>(dst);                 // #2
    k_scan<<<1, 1024, 0, s_aux>>>();                                  // #3

    // #4 (profiled slot): layer-1 GEMM (N=256 = [xl|xr])
    gemm_f16<128><<<dim3(2, MB), 256, SMEM128>>>(xhi, xlo, wt1h, cb1, xlr1, NN, 256, 128);

    k_scatter<<<(NE + 255) / 256, 256, 0, s_aux>>>(src, dst);         // #5
    cudaEventRecord(e_csr, s_aux);
    cudaStreamWaitEvent(0, e_csr, 0);

    k_agg<128, 1><<<(NN * 1 + 7) / 8, 256>>>(xlr1, 256, 128, att1, bias1, h1hi, h1lo);
    gemm_f16<128><<<dim3(8, MB), 256, SMEM128>>>(h1hi, h1lo, wt2h, cb2, xlr2, NN, 1024, 128);
    k_agg<512, 2><<<(NN * 2 + 7) / 8, 256>>>(xlr2, 1024, 512, att2, bias2, h2hi, h2lo);
    gemm_f16<64><<<dim3(1, MB), 256, SMEM64>>>(h2hi, h2lo, wtlh, blin, out, NN, 64, 512);
}